// round 3
// baseline (speedup 1.0000x reference)
#include <cuda_runtime.h>
#include <cstdint>

#define Nn 768
#define Hh 32
#define Ee 24576
#define Pp 4096
#define NCH 8
#define CW 96
#define NW 24            // 768/32 adjacency words per row
#define NBLK 96
#define NBT (NBLK*256)
#define MAXPAIR (1<<21)  // 2M pair records (actual ~800K)

// ---------------- scratch ----------------
__device__ unsigned d_abits[Nn*NW];        // adjacency bitmask (dedup)
__device__ unsigned d_nbits[Nn*NW];        // pos-needed bitmask (symmetric)
__device__ unsigned char d_maskb[Nn*Nn];
__device__ float d_dinv[Nn];
__device__ float d_h [Nn*Hh];
__device__ float d_hT[Nn*Hh];
__device__ int   d_cnt2[Nn*NCH];
__device__ int   d_base[Nn*NCH+1];
__device__ int   d_fill[Nn*NCH];
__device__ int   d_pcnt[Nn*NCH];
__device__ int   d_pbase[Nn*NCH+1];
__device__ int   d_col[Ee];
__device__ int   d_cu [Ee];
__device__ int2  d_pair[MAXPAIR];          // {e, f | j<<16}
__device__ float d_xe [Ee*Hh];
__device__ float d_mul[Ee*Hh];
__device__ float d_z  [(size_t)Nn*Nn*Hh];
__device__ float d_p1[NBLK*Hh], d_p2[NBLK*Hh];
__device__ float d_S1[Hh], d_S2[Hh];
__device__ int   d_cntM;
__device__ int   d_barcnt;                  // reset by k_rowC each replay

// ---------------- f32x2 helpers ----------------
__device__ __forceinline__ void fma2(unsigned long long& d, unsigned long long a, unsigned long long b){
    asm("fma.rn.f32x2 %0, %1, %2, %0;" : "+l"(d) : "l"(a), "l"(b));
}
__device__ __forceinline__ unsigned long long pk2(float lo, float hi){
    unsigned long long r; asm("mov.b64 %0,{%1,%2};" : "=l"(r) : "f"(lo), "f"(hi)); return r;
}
__device__ __forceinline__ float upk_sum(unsigned long long v){
    float lo, hi; asm("mov.b64 {%0,%1},%2;" : "=f"(lo), "=f"(hi) : "l"(v)); return lo+hi;
}

// ---------------- soft grid barrier (96 resident blocks) ----------------
__device__ __forceinline__ void gbar(int phase) {
    __threadfence();
    __syncthreads();
    if (threadIdx.x == 0) {
        atomicAdd(&d_barcnt, 1);
        int target = phase * NBLK;
        while (*(volatile int*)&d_barcnt < target) __nanosleep(32);
        __threadfence();
    }
    __syncthreads();
}

// ---------------- mega: setup + CSR + pair counts + GCN ----------------
__global__ void __launch_bounds__(256) k_mega(
    const int* __restrict__ x, const int* __restrict__ ei, const int* __restrict__ pos,
    const float* __restrict__ emb, const float* __restrict__ gcnW, const float* __restrict__ gcnb)
{
    __shared__ float red1[8][32], red2[8][32];
    __shared__ float sMean[32], sInv[32];
    __shared__ int stot[257];

    int tid = threadIdx.x, w = tid>>5, lane = tid&31;
    int bid = blockIdx.x;
    int gtid = bid*256 + tid;
    int gw = bid*8 + w;                 // row per warp

    // P0: zero + embed
    {
        int4 z4 = make_int4(0,0,0,0);
        for (int t=gtid; t<Nn*NW/4; t+=NBT){ ((int4*)d_abits)[t]=z4; ((int4*)d_nbits)[t]=z4; }
        for (int t=gtid; t<Nn*NCH; t+=NBT) d_cnt2[t]=0;
        if (gtid < Hh){ d_S1[gtid]=0.f; d_S2[gtid]=0.f; }
        if (gtid == 0) d_cntM = 0;
    }
    float hval = emb[x[gw]*Hh+lane];
    gbar(1);

    // P1: scatter adjacency bits + chunk counts + need bits
    if (gtid < Ee){
        int u=ei[gtid], v=ei[Ee+gtid];
        atomicOr(&d_abits[u*NW+(v>>5)], 1u<<(v&31));
        atomicAdd(&d_cnt2[u*NCH + v/CW], 1);
    }
    if (gtid < Pp){
        int a=pos[2*gtid], b=pos[2*gtid+1];
        atomicOr(&d_nbits[a*NW+(b>>5)], 1u<<(b&31));
        atomicOr(&d_nbits[b*NW+(a>>5)], 1u<<(a&31));
    }
    gbar(2);

    // P2: dinv (all) + cnt2 scan (block 0)
    {
        int s = (lane < NW) ? __popc(d_abits[gw*NW+lane]) : 0;
        for (int o=16;o;o>>=1) s += __shfl_down_sync(0xffffffffu, s, o);
        if (lane==0) d_dinv[gw] = rsqrtf((float)s + 1.0f);
    }
    if (bid == 0) {
        int lo = tid*24; int vals[24]; int run = 0;
        #pragma unroll
        for (int q=0;q<24;q++){ vals[q]=run; run += d_cnt2[lo+q]; }
        stot[tid] = run; __syncthreads();
        if (tid==0){ int r=0; for (int t=0;t<256;t++){ int xx=stot[t]; stot[t]=r; r+=xx; } stot[256]=r; }
        __syncthreads();
        int base = stot[tid];
        #pragma unroll
        for (int q=0;q<24;q++){ int vv = base+vals[q]; d_base[lo+q]=vv; d_fill[lo+q]=vv; }
        if (tid==0) d_base[Nn*NCH] = stot[256];
    }
    gbar(3);

    // P3: fill CSR
    if (gtid < Ee){
        int u=ei[gtid], v=ei[Ee+gtid];
        int s = atomicAdd(&d_fill[u*NCH+v/CW],1);
        d_col[s]=v; d_cu[s]=u;
    }
    gbar(4);

    // P4: pair counts per (row, chunk) — slot-exact (duplicates counted)
    {
        int es = d_base[gw*NCH], ee2 = d_base[(gw+1)*NCH];
        int c = lane&7, g = lane>>3, s = 0;
        for (int e=es+g; e<ee2; e+=4) s += d_cnt2[d_col[e]*NCH + c];
        s += __shfl_down_sync(0xffffffffu, s, 16);
        s += __shfl_down_sync(0xffffffffu, s, 8);
        if (lane < 8) d_pcnt[gw*NCH+lane] = s;
    }
    gbar(5);

    // GCN: 2 layers; block 0 also scans pcnt in the first hW window
    int ph = 5;
    #pragma unroll 1
    for (int l=0; l<2; l++) {
        const float* W = gcnW + l*Hh*Hh;
        float acc = 0.f;
        #pragma unroll
        for (int k=0;k<32;k++) acc += __shfl_sync(0xffffffffu, hval, k) * W[k*Hh+lane];
        float dv = d_dinv[gw];
        float self = dv*acc;
        d_hT[gw*Hh+lane] = self;
        if (l==0 && bid==0) {            // pcnt scan folded into this window
            int lo = tid*24; int vals[24]; int run = 0;
            #pragma unroll
            for (int q=0;q<24;q++){ vals[q]=run; run += d_pcnt[lo+q]; }
            stot[tid] = run; __syncthreads();
            if (tid==0){ int r=0; for (int t=0;t<256;t++){ int xx=stot[t]; stot[t]=r; r+=xx; } stot[256]=r; }
            __syncthreads();
            int base = stot[tid];
            #pragma unroll
            for (int q=0;q<24;q++) d_pbase[lo+q] = base+vals[q];
            if (tid==0) d_pbase[Nn*NCH] = stot[256];
        }
        gbar(++ph);

        float aggv = 0.f;
        #pragma unroll 1
        for (int wd=0; wd<NW; wd++){
            unsigned m = d_abits[gw*NW+wd];
            int jb = wd*32;
            while (m){ int b=__ffs(m)-1; m&=m-1; aggv += d_hT[(jb+b)*Hh+lane]; }
        }
        float v = dv*(aggv + self) + gcnb[l*Hh+lane];

        red1[w][lane]=v; red2[w][lane]=v*v;
        __syncthreads();
        if (w==0){
            float s1=0.f, s2=0.f;
            #pragma unroll
            for (int r=0;r<8;r++){ s1+=red1[r][lane]; s2+=red2[r][lane]; }
            d_p1[bid*32+lane]=s1; d_p2[bid*32+lane]=s2;
        }
        gbar(++ph);

        if (w==0){
            float s1=0.f, s2=0.f;
            for (int b=0;b<NBLK;b++){ s1+=d_p1[b*32+lane]; s2+=d_p2[b*32+lane]; }
            float mean = s1/(float)Nn;
            sMean[lane]=mean; sInv[lane]=rsqrtf(s2/(float)Nn - mean*mean + 1e-5f);
        }
        __syncthreads();
        hval = fmaxf((v - sMean[lane])*sInv[lane], 0.f);
        __syncthreads();
    }
    d_h[gw*Hh+lane] = hval;
}

// ---------------- fill flat pair lists (warp per row) ----------------
__global__ void __launch_bounds__(256) k_fillpairs() {
    int w = threadIdx.x>>5, lane = threadIdx.x&31;
    int gw = blockIdx.x*8 + w;
    int cur[NCH];
    #pragma unroll
    for (int c=0;c<NCH;c++) cur[c] = d_pbase[gw*NCH+c];
    int es = d_base[gw*NCH], ee = d_base[(gw+1)*NCH];
    for (int e=es; e<ee; e++){
        int k = d_col[e];
        #pragma unroll
        for (int c=0;c<NCH;c++){
            int fs = d_base[k*NCH+c];
            int len = d_base[k*NCH+c+1] - fs;
            for (int t=lane; t<len; t+=32){
                int f = fs + t;
                d_pair[cur[c]+t] = make_int2(e, f | (d_col[f]<<16));
            }
            cur[c] += len;
        }
    }
}

// ---------------- edge MLPs (high occupancy, warp per edge-slot) ----------------
__global__ void __launch_bounds__(256) k_mlp(
    const float* __restrict__ W1, const float* __restrict__ b1,
    const float* __restrict__ W2, const float* __restrict__ b2)
{
    int w = threadIdx.x>>5, lane = threadIdx.x&31;
    int s = blockIdx.x*8 + w;
    int u = d_cu[s], v = d_col[s];
    float hu = d_h[u*Hh+lane], hv = d_h[v*Hh+lane];
    float x1 = b1[lane], x2 = b2[lane];
    #pragma unroll
    for (int k=0;k<32;k++){
        float a = __shfl_sync(0xffffffffu,hu,k);
        float b = __shfl_sync(0xffffffffu,hv,k);
        x1 += a*W1[k*Hh+lane] + b*W1[(k+32)*Hh+lane];
        x2 += a*W2[k*Hh+lane] + b*W2[(k+32)*Hh+lane];
    }
    d_xe [s*Hh+lane]=fmaxf(x1,0.f);
    d_mul[s*Hh+lane]=fmaxf(x2,0.f);
}

// ---------------- hot kernel: flat-pair 2-hop C + z + masked moments ----------------
__global__ void __launch_bounds__(256,2) k_rowC(const float* __restrict__ W3,
                                                const float* __restrict__ b3v) {
    extern __shared__ float Cs[];                  // Nn*Hh floats; warp w owns rows [96w,96w+96)
    __shared__ float sr1[8][32], sr2[8][32];
    __shared__ int src[8];
    int tid = threadIdx.x, w = tid>>5, lane = tid&31;
    int i = blockIdx.x;

    if (i==0 && tid==0) d_barcnt = 0;              // reset mega barrier for next replay

    // zero own chunk only (no cross-warp deps -> no __syncthreads needed)
    {
        float4 z4 = make_float4(0.f,0.f,0.f,0.f);
        float4* Cz = (float4*)(Cs + w*CW*Hh);
        #pragma unroll
        for (int t=lane; t<CW*Hh/4; t+=32) Cz[t]=z4;
    }

    // phase 2: flat streaming accumulation over this warp's pair list
    int ps = d_pbase[i*NCH+w], pe = d_pbase[i*NCH+w+1];
    unsigned tb0=0, tb1=0, tb2=0;                  // touched bits for own 96 j's
    #pragma unroll 4
    for (int t=ps; t<pe; t++){
        int2 pr = __ldg(&d_pair[t]);
        float xv = d_xe[(size_t)pr.x*Hh + lane];
        int f  = pr.y & 0xFFFF;
        int jj = pr.y >> 16;
        float mv = d_mul[(size_t)f*Hh + lane];
        Cs[jj*Hh+lane] += xv*mv;
        int b = jj - w*CW;                         // warp-uniform
        if (b < 32)      tb0 |= 1u<<b;
        else if (b < 64) tb1 |= 1u<<(b-32);
        else             tb2 |= 1u<<(b-64);
    }

    // phase 3: z = C@W3 + af*W3[32] + b3 via packed f32x2; moments; sparse z store
    unsigned long long w2[16];
    #pragma unroll
    for (int t=0;t<16;t++) w2[t] = pk2(W3[(2*t)*Hh+lane], W3[(2*t+1)*Hh+lane]);
    float w3last = W3[32*Hh+lane];
    float bb = b3v[lane];
    float s1=0.f, s2=0.f; int c0=0;
    const size_t zrow = (size_t)i*Nn;

    unsigned tbs[3] = {tb0, tb1, tb2};
    #pragma unroll
    for (int t=0;t<3;t++){
        int j0 = w*CW + t*32;
        unsigned mA = d_abits[i*NW + w*3 + t];
        unsigned mM = mA | tbs[t];
        unsigned mN = d_nbits[i*NW + w*3 + t] & mM;
        d_maskb[i*Nn + j0 + lane] = (unsigned char)((mM>>lane)&1u);
        c0 += __popc(mM);
        unsigned rem = mM;
        while (rem){
            int b = __ffs(rem)-1; rem &= rem-1;
            int jj = j0 + b;
            const ulonglong2* Cj = (const ulonglong2*)(Cs + jj*Hh);
            unsigned long long a0 = 0ull, a1 = 0ull;
            #pragma unroll
            for (int q=0;q<4;q++){
                ulonglong2 cA = Cj[q];
                ulonglong2 cB = Cj[q+4];
                fma2(a0, cA.x, w2[2*q]);   fma2(a0, cA.y, w2[2*q+1]);
                fma2(a1, cB.x, w2[2*q+8]); fma2(a1, cB.y, w2[2*q+9]);
            }
            float acc = bb + upk_sum(a0) + upk_sum(a1) + (((mA>>b)&1u) ? w3last : 0.f);
            s1 += acc; s2 += acc*acc;
            if ((mN>>b)&1u) d_z[(zrow+jj)*Hh+lane] = acc;
        }
    }
    sr1[w][lane]=s1; sr2[w][lane]=s2; if (lane==0) src[w]=c0;
    __syncthreads();
    if (w==0){
        float a=0.f, b=0.f;
        #pragma unroll
        for (int r=0;r<8;r++){ a+=sr1[r][lane]; b+=sr2[r][lane]; }
        atomicAdd(&d_S1[lane], a);
        atomicAdd(&d_S2[lane], b);
        if (lane==0){ int cc=0; for (int r=0;r<8;r++) cc+=src[r]; atomicAdd(&d_cntM, cc); }
    }
}

// ---------------- output ----------------
__global__ void k_pos(const int* __restrict__ pos, const float* __restrict__ linW,
                      const float* __restrict__ linb, float* __restrict__ out) {
    int w = threadIdx.x>>5, lane = threadIdx.x&31;
    int p = blockIdx.x*8 + w;
    float cnt = (float)d_cntM;
    float mean = d_S1[lane]/cnt;
    float inv  = rsqrtf(d_S2[lane]/cnt - mean*mean + 1e-5f);
    int p0 = pos[2*p], p1 = pos[2*p+1];
    float acc = d_h[p0*Hh+lane]*d_h[p1*Hh+lane]*linW[Hh+lane];
    if (d_maskb[p0*Nn+p1]) {
        float z1 = d_z[((size_t)p0*Nn+p1)*Hh+lane];
        float z2 = d_z[((size_t)p1*Nn+p0)*Hh+lane];
        acc += fmaxf((z1-mean)*inv,0.f)*fmaxf((z2-mean)*inv,0.f)*linW[lane];
    }
    for (int o=16;o;o>>=1) acc += __shfl_down_sync(0xffffffffu, acc, o);
    if (lane==0) out[p] = acc + linb[0];
}

// ---------------- launch ----------------
extern "C" void kernel_launch(void* const* d_in, const int* in_sizes, int n_in,
                              void* d_out, int out_size) {
    const int*   x    = (const int*)  d_in[0];
    const int*   ei   = (const int*)  d_in[1];
    const int*   pos  = (const int*)  d_in[2];
    const float* emb  = (const float*)d_in[3];
    const float* gcnW = (const float*)d_in[4];
    const float* gcnb = (const float*)d_in[5];
    const float* W1   = (const float*)d_in[6];
    const float* b1   = (const float*)d_in[7];
    const float* W2   = (const float*)d_in[8];
    const float* b2   = (const float*)d_in[9];
    const float* W3   = (const float*)d_in[10];
    const float* b3   = (const float*)d_in[11];
    const float* linW = (const float*)d_in[12];
    const float* linb = (const float*)d_in[13];
    float* out = (float*)d_out;

    const int smemC = Nn*Hh*(int)sizeof(float);   // 96 KB
    cudaFuncSetAttribute(k_rowC, cudaFuncAttributeMaxDynamicSharedMemorySize, smemC);

    k_mega     <<<NBLK,256>>>(x, ei, pos, emb, gcnW, gcnb);
    k_fillpairs<<<NBLK,256>>>();
    k_mlp      <<<Ee/8,256>>>(W1,b1,W2,b2);
    k_rowC     <<<Nn,256,smemC>>>(W3,b3);
    k_pos      <<<Pp/8,256>>>(pos, linW, linb, out);
}

// round 4
// speedup vs baseline: 1.0842x; 1.0842x over previous
#include <cuda_runtime.h>

#define Nn 768
#define Hh 32
#define Ee 24576
#define Pp 4096
#define NW 24              // 768/32 bitmask words per row
#define NBLK 96
#define NBT (NBLK*256)
#define MAXPAIR (1<<21)

// ---------------- scratch ----------------
__device__ unsigned d_abits[Nn*NW];
__device__ unsigned d_nbits[Nn*NW];
__device__ unsigned char d_maskb[Nn*Nn];
__device__ float d_dinv[Nn];
__device__ float d_h [Nn*Hh];
__device__ float d_hT[Nn*Hh];
__device__ int   d_cnt [Nn];
__device__ int   d_base[Nn+1];
__device__ int   d_fillc[Nn];
__device__ int   d_col[Ee];
__device__ int   d_cu [Ee];
__device__ int   d_ijbase[Nn*Nn];       // counts -> in-place scanned starts
__device__ int   d_ijfill[Nn*Nn];       // fill cursor; after fill = segment end
__device__ int   d_rowtot[Nn];
__device__ int   d_rowbase[Nn];
__device__ int   d_pairs[MAXPAIR];      // e | f<<16
__device__ float d_xe [Ee*Hh];
__device__ float d_mul[Ee*Hh];
__device__ float d_z  [(size_t)Nn*Nn*Hh];
__device__ float d_p1[NBLK*Hh], d_p2[NBLK*Hh];
__device__ float d_S1[Hh], d_S2[Hh];
__device__ int   d_cntM;
__device__ int   d_barcnt;              // reset by k_pos each replay

// ---------------- f32x2 helpers ----------------
__device__ __forceinline__ void fma2(unsigned long long& d, unsigned long long a, unsigned long long b){
    asm("fma.rn.f32x2 %0, %1, %2, %0;" : "+l"(d) : "l"(a), "l"(b));
}
__device__ __forceinline__ unsigned long long pk2(float lo, float hi){
    unsigned long long r; asm("mov.b64 %0,{%1,%2};" : "=l"(r) : "f"(lo), "f"(hi)); return r;
}
__device__ __forceinline__ float upk_sum(unsigned long long v){
    float lo, hi; asm("mov.b64 {%0,%1},%2;" : "=f"(lo), "=f"(hi) : "l"(v)); return lo+hi;
}

// ---------------- soft grid barrier (96 resident blocks) ----------------
__device__ __forceinline__ void gbar(int phase) {
    __threadfence();
    __syncthreads();
    if (threadIdx.x == 0) {
        atomicAdd(&d_barcnt, 1);
        int target = phase * NBLK;
        while (*(volatile int*)&d_barcnt < target) __nanosleep(32);
        __threadfence();
    }
    __syncthreads();
}

// ---------------- mega: setup + CSR + (i,j) pair machinery + GCN ----------------
__global__ void __launch_bounds__(256) k_mega(
    const int* __restrict__ x, const int* __restrict__ ei, const int* __restrict__ pos,
    const float* __restrict__ emb, const float* __restrict__ gcnW, const float* __restrict__ gcnb)
{
    __shared__ float red1[8][32], red2[8][32];
    __shared__ float sMean[32], sInv[32];
    __shared__ int stot[257];

    int tid = threadIdx.x, w = tid>>5, lane = tid&31;
    int bid = blockIdx.x;
    int gtid = bid*256 + tid;           // 0..24575 == Ee
    int gw = bid*8 + w;                 // 0..767 row per warp

    // P0: zero scratch + embed (hval in registers)
    {
        int4 z4 = make_int4(0,0,0,0);
        for (int t=gtid; t<Nn*NW/4; t+=NBT){ ((int4*)d_abits)[t]=z4; ((int4*)d_nbits)[t]=z4; }
        for (int t=gtid; t<Nn*Nn/4; t+=NBT) ((int4*)d_ijbase)[t]=z4;
        if (gtid < Nn) d_cnt[gtid]=0;
        if (gtid < Hh){ d_S1[gtid]=0.f; d_S2[gtid]=0.f; }
        if (gtid == 0) d_cntM = 0;
    }
    float hval = emb[x[gw]*Hh+lane];
    gbar(1);

    // P1: scatter adjacency bits + row counts + need bits
    { int u=ei[gtid], v=ei[Ee+gtid];
      atomicOr(&d_abits[u*NW+(v>>5)], 1u<<(v&31));
      atomicAdd(&d_cnt[u], 1); }
    if (gtid < Pp){
        int a=pos[2*gtid], b=pos[2*gtid+1];
        atomicOr(&d_nbits[a*NW+(b>>5)], 1u<<(b&31));
        atomicOr(&d_nbits[b*NW+(a>>5)], 1u<<(a&31));
    }
    gbar(2);

    // P2: dinv (all) + CSR row scan (block 0)
    {
        int s = (lane < NW) ? __popc(d_abits[gw*NW+lane]) : 0;
        for (int o=16;o;o>>=1) s += __shfl_down_sync(0xffffffffu, s, o);
        if (lane==0) d_dinv[gw] = rsqrtf((float)s + 1.0f);
    }
    if (bid == 0) {
        int lo = tid*3; int v0=d_cnt[lo], v1=d_cnt[lo+1], v2=d_cnt[lo+2];
        stot[tid] = v0+v1+v2; __syncthreads();
        if (tid==0){ int r=0; for (int t=0;t<256;t++){ int xx=stot[t]; stot[t]=r; r+=xx; } stot[256]=r; }
        __syncthreads();
        int b0 = stot[tid];
        d_base[lo]=b0; d_base[lo+1]=b0+v0; d_base[lo+2]=b0+v0+v1;
        d_fillc[lo]=b0; d_fillc[lo+1]=b0+v0; d_fillc[lo+2]=b0+v0+v1;
        if (tid==0) d_base[Nn] = stot[256];
    }
    gbar(3);

    // P3: fill CSR
    { int u=ei[gtid], v=ei[Ee+gtid];
      int s = atomicAdd(&d_fillc[u],1);
      d_col[s]=v; d_cu[s]=u; }
    gbar(4);

    // P4: per-(i,j) pair counts (slot-exact; duplicates counted)
    {
        int es = d_base[gw], ee = d_base[gw+1];
        for (int e=es; e<ee; e++){
            int k = d_col[e];
            int fs = d_base[k], fe = d_base[k+1];
            for (int f=fs+lane; f<fe; f+=32)
                atomicAdd(&d_ijbase[gw*Nn + d_col[f]], 1);
        }
    }
    gbar(5);

    // P5: in-place exclusive scan of each row's 768 counts (warp per row) + row totals
    {
        int off = 0;
        #pragma unroll 1
        for (int c=0;c<NW;c++){
            int idx = gw*Nn + c*32 + lane;
            int v = d_ijbase[idx];
            int s = v;
            #pragma unroll
            for (int o=1;o<32;o<<=1){ int t2=__shfl_up_sync(0xffffffffu,s,o); if (lane>=o) s+=t2; }
            d_ijbase[idx] = off + s - v;
            off += __shfl_sync(0xffffffffu, s, 31);
        }
        if (lane==0) d_rowtot[gw]=off;
    }
    gbar(6);

    // P6: hW layer0 (all) + rowtot scan (block 0)
    {
        const float* W = gcnW;
        float acc = 0.f;
        #pragma unroll
        for (int k=0;k<32;k++) acc += __shfl_sync(0xffffffffu, hval, k) * W[k*Hh+lane];
        d_hT[gw*Hh+lane] = d_dinv[gw]*acc;
    }
    if (bid == 0) {
        int lo = tid*3; int v0=d_rowtot[lo], v1=d_rowtot[lo+1], v2=d_rowtot[lo+2];
        stot[tid] = v0+v1+v2; __syncthreads();
        if (tid==0){ int r=0; for (int t=0;t<256;t++){ int xx=stot[t]; stot[t]=r; r+=xx; } }
        __syncthreads();
        int b0 = stot[tid];
        d_rowbase[lo]=b0; d_rowbase[lo+1]=b0+v0; d_rowbase[lo+2]=b0+v0+v1;
    }
    gbar(7);

    // P7: add rowbase + copy cursors ; agg layer0 + partials
    for (int t=gtid; t<Nn*Nn; t+=NBT){
        int i = t/Nn;
        int v = d_ijbase[t] + d_rowbase[i];
        d_ijbase[t]=v; d_ijfill[t]=v;
    }
    float vgcn;
    {
        float aggv = 0.f;
        #pragma unroll 1
        for (int wd=0; wd<NW; wd++){
            unsigned m = d_abits[gw*NW+wd];
            int jb = wd*32;
            while (m){ int b=__ffs(m)-1; m&=m-1; aggv += d_hT[(jb+b)*Hh+lane]; }
        }
        vgcn = d_dinv[gw]*(aggv + d_hT[gw*Hh+lane]) + gcnb[lane];
        red1[w][lane]=vgcn; red2[w][lane]=vgcn*vgcn;
        __syncthreads();
        if (w==0){
            float s1=0.f, s2=0.f;
            #pragma unroll
            for (int r=0;r<8;r++){ s1+=red1[r][lane]; s2+=red2[r][lane]; }
            d_p1[bid*32+lane]=s1; d_p2[bid*32+lane]=s2;
        }
    }
    gbar(8);

    // P8: norm0 apply ; fill (i,j) pair lists
    {
        if (w==0){
            float s1=0.f, s2=0.f;
            for (int b=0;b<NBLK;b++){ s1+=d_p1[b*32+lane]; s2+=d_p2[b*32+lane]; }
            float mean = s1/(float)Nn;
            sMean[lane]=mean; sInv[lane]=rsqrtf(s2/(float)Nn - mean*mean + 1e-5f);
        }
        __syncthreads();
        hval = fmaxf((vgcn - sMean[lane])*sInv[lane], 0.f);
        __syncthreads();
    }
    {
        int es = d_base[gw], ee = d_base[gw+1];
        for (int e=es; e<ee; e++){
            int k = d_col[e];
            int fs = d_base[k], fe = d_base[k+1];
            for (int f=fs+lane; f<fe; f+=32){
                int j = d_col[f];
                int slot = atomicAdd(&d_ijfill[gw*Nn+j],1);
                d_pairs[slot] = e | (f<<16);
            }
        }
    }
    gbar(9);

    // P9: hW layer1
    {
        const float* W = gcnW + Hh*Hh;
        float acc = 0.f;
        #pragma unroll
        for (int k=0;k<32;k++) acc += __shfl_sync(0xffffffffu, hval, k) * W[k*Hh+lane];
        d_hT[gw*Hh+lane] = d_dinv[gw]*acc;
    }
    gbar(10);

    // P10: agg layer1 + partials
    {
        float aggv = 0.f;
        #pragma unroll 1
        for (int wd=0; wd<NW; wd++){
            unsigned m = d_abits[gw*NW+wd];
            int jb = wd*32;
            while (m){ int b=__ffs(m)-1; m&=m-1; aggv += d_hT[(jb+b)*Hh+lane]; }
        }
        vgcn = d_dinv[gw]*(aggv + d_hT[gw*Hh+lane]) + gcnb[Hh+lane];
        red1[w][lane]=vgcn; red2[w][lane]=vgcn*vgcn;
        __syncthreads();
        if (w==0){
            float s1=0.f, s2=0.f;
            #pragma unroll
            for (int r=0;r<8;r++){ s1+=red1[r][lane]; s2+=red2[r][lane]; }
            d_p1[bid*32+lane]=s1; d_p2[bid*32+lane]=s2;
        }
    }
    gbar(11);

    // P11: norm1 apply -> d_h
    {
        if (w==0){
            float s1=0.f, s2=0.f;
            for (int b=0;b<NBLK;b++){ s1+=d_p1[b*32+lane]; s2+=d_p2[b*32+lane]; }
            float mean = s1/(float)Nn;
            sMean[lane]=mean; sInv[lane]=rsqrtf(s2/(float)Nn - mean*mean + 1e-5f);
        }
        __syncthreads();
        d_h[gw*Hh+lane] = fmaxf((vgcn - sMean[lane])*sInv[lane], 0.f);
    }
}

// ---------------- edge MLPs (warp per edge-slot, 3072 blocks) ----------------
__global__ void __launch_bounds__(256) k_mlp(
    const float* __restrict__ W1, const float* __restrict__ b1,
    const float* __restrict__ W2, const float* __restrict__ b2)
{
    int w = threadIdx.x>>5, lane = threadIdx.x&31;
    int s = blockIdx.x*8 + w;
    int u = d_cu[s], v = d_col[s];
    float hu = d_h[u*Hh+lane], hv = d_h[v*Hh+lane];
    float x1 = b1[lane], x2 = b2[lane];
    #pragma unroll
    for (int k=0;k<32;k++){
        float a = __shfl_sync(0xffffffffu,hu,k);
        float b = __shfl_sync(0xffffffffu,hv,k);
        x1 += a*W1[k*Hh+lane] + b*W1[(k+32)*Hh+lane];
        x2 += a*W2[k*Hh+lane] + b*W2[(k+32)*Hh+lane];
    }
    d_xe [s*Hh+lane]=fmaxf(x1,0.f);
    d_mul[s*Hh+lane]=fmaxf(x2,0.f);
}

// ---------------- hot kernel: per-(i,j) register-resident C + z + moments ----------------
// warp handles 32 consecutive (i,j) entries (all in one row: 768 = 24*32)
__global__ void __launch_bounds__(256) k_z(const float* __restrict__ W3,
                                           const float* __restrict__ b3v) {
    __shared__ float sC[8][32];
    __shared__ float sr1[8][32], sr2[8][32];
    __shared__ int src[8];
    int tid = threadIdx.x, w = tid>>5, lane = tid&31;
    int wid = blockIdx.x*8 + w;          // 0..18431
    int i = wid/24;
    int ij0 = i*Nn + (wid%24)*32;

    // per-lane meta for this warp's 32 entries (coalesced)
    int start = d_ijbase[ij0+lane];
    int end   = d_ijfill[ij0+lane];
    unsigned mA = d_abits[i*NW + ((ij0 - i*Nn)>>5)];   // warp-uniform word
    unsigned mN = d_nbits[i*NW + ((ij0 - i*Nn)>>5)];
    unsigned hasP = __ballot_sync(0xffffffffu, end>start);
    unsigned mM = mA | hasP;
    d_maskb[ij0+lane] = (unsigned char)((mM>>lane)&1u);
    int c0 = __popc(mM);

    float s1=0.f, s2=0.f;
    if (mM) {
        unsigned long long w2[16];
        #pragma unroll
        for (int t=0;t<16;t++) w2[t] = pk2(W3[(2*t)*Hh+lane], W3[(2*t+1)*Hh+lane]);
        float w3last = W3[32*Hh+lane];
        float bb = b3v[lane];

        unsigned rem = mM;
        while (rem){
            int b = __ffs(rem)-1; rem &= rem-1;
            int st = __shfl_sync(0xffffffffu, start, b);
            int en = __shfl_sync(0xffffffffu, end, b);
            float C = 0.f;
            #pragma unroll 2
            for (int t=st; t<en; t++){
                int p = d_pairs[t];
                C += d_xe[(size_t)(p & 0xFFFF)*Hh + lane] * d_mul[(size_t)(p>>16)*Hh + lane];
            }
            sC[w][lane] = C;
            __syncwarp();
            const ulonglong2* Cj = (const ulonglong2*)sC[w];
            unsigned long long a0 = 0ull, a1 = 0ull;
            #pragma unroll
            for (int q=0;q<4;q++){
                ulonglong2 cA = Cj[q];
                ulonglong2 cB = Cj[q+4];
                fma2(a0, cA.x, w2[2*q]);   fma2(a0, cA.y, w2[2*q+1]);
                fma2(a1, cB.x, w2[2*q+8]); fma2(a1, cB.y, w2[2*q+9]);
            }
            __syncwarp();
            float acc = bb + upk_sum(a0) + upk_sum(a1) + (((mA>>b)&1u) ? w3last : 0.f);
            s1 += acc; s2 += acc*acc;
            if ((mN>>b)&1u) d_z[(size_t)(ij0+b)*Hh + lane] = acc;
        }
    }
    sr1[w][lane]=s1; sr2[w][lane]=s2; if (lane==0) src[w]=c0;
    __syncthreads();
    if (w==0){
        float a=0.f, b=0.f;
        #pragma unroll
        for (int r=0;r<8;r++){ a+=sr1[r][lane]; b+=sr2[r][lane]; }
        atomicAdd(&d_S1[lane], a);
        atomicAdd(&d_S2[lane], b);
        if (lane==0){ int cc=0; for (int r=0;r<8;r++) cc+=src[r]; atomicAdd(&d_cntM, cc); }
    }
}

// ---------------- output ----------------
__global__ void k_pos(const int* __restrict__ pos, const float* __restrict__ linW,
                      const float* __restrict__ linb, float* __restrict__ out) {
    int w = threadIdx.x>>5, lane = threadIdx.x&31;
    int p = blockIdx.x*8 + w;
    if (blockIdx.x==0 && threadIdx.x==0) d_barcnt = 0;   // reset mega barrier for next replay
    float cnt = (float)d_cntM;
    float mean = d_S1[lane]/cnt;
    float inv  = rsqrtf(d_S2[lane]/cnt - mean*mean + 1e-5f);
    int p0 = pos[2*p], p1 = pos[2*p+1];
    float acc = d_h[p0*Hh+lane]*d_h[p1*Hh+lane]*linW[Hh+lane];
    if (d_maskb[p0*Nn+p1]) {
        float z1 = d_z[((size_t)p0*Nn+p1)*Hh+lane];
        float z2 = d_z[((size_t)p1*Nn+p0)*Hh+lane];
        acc += fmaxf((z1-mean)*inv,0.f)*fmaxf((z2-mean)*inv,0.f)*linW[lane];
    }
    for (int o=16;o;o>>=1) acc += __shfl_down_sync(0xffffffffu, acc, o);
    if (lane==0) out[p] = acc + linb[0];
}

// ---------------- launch ----------------
extern "C" void kernel_launch(void* const* d_in, const int* in_sizes, int n_in,
                              void* d_out, int out_size) {
    const int*   x    = (const int*)  d_in[0];
    const int*   ei   = (const int*)  d_in[1];
    const int*   pos  = (const int*)  d_in[2];
    const float* emb  = (const float*)d_in[3];
    const float* gcnW = (const float*)d_in[4];
    const float* gcnb = (const float*)d_in[5];
    const float* W1   = (const float*)d_in[6];
    const float* b1   = (const float*)d_in[7];
    const float* W2   = (const float*)d_in[8];
    const float* b2   = (const float*)d_in[9];
    const float* W3   = (const float*)d_in[10];
    const float* b3   = (const float*)d_in[11];
    const float* linW = (const float*)d_in[12];
    const float* linb = (const float*)d_in[13];
    float* out = (float*)d_out;

    k_mega<<<NBLK,256>>>(x, ei, pos, emb, gcnW, gcnb);
    k_mlp <<<Ee/8,256>>>(W1,b1,W2,b2);
    k_z   <<<Nn*NW/8,256>>>(W3,b3);
    k_pos <<<Pp/8,256>>>(pos, linW, linb, out);
}

// round 6
// speedup vs baseline: 1.4160x; 1.3061x over previous
#include <cuda_runtime.h>

#define Nn 768
#define Hh 32
#define Ee 24576
#define Pp 4096
#define NW 24              // 768/32 bitmask words per row
#define BUD 6144           // per-row pair budget
#define NAGG 192

// ---------------- scratch ----------------
__device__ unsigned d_abits[Nn*NW];
__device__ unsigned d_nbits[Nn*NW];
__device__ unsigned char d_maskb[Nn*Nn];
__device__ float d_dinv[Nn];
__device__ float d_h [Nn*Hh];
__device__ float d_hT[Nn*Hh];
__device__ float d_hP[Nn*Hh];
__device__ int   d_cnt [Nn];
__device__ int   d_base[Nn+1];
__device__ int   d_fillc[Nn];
__device__ int   d_col[Ee];
__device__ int   d_cu [Ee];
__device__ int   d_ijstart[Nn*Nn];     // local (within-row) segment starts
__device__ int   d_ijend  [Nn*Nn];
__device__ int   d_pairs[Nn*BUD];      // e | f<<16
__device__ float d_xe [Ee*Hh];
__device__ float d_mul[Ee*Hh];
__device__ float d_z  [(size_t)Nn*Nn*Hh];
__device__ float d_p1[NAGG*Hh], d_p2[NAGG*Hh];
__device__ float d_S1[Hh], d_S2[Hh];
__device__ int   d_cntM;

// ---------------- f32x2 helpers ----------------
__device__ __forceinline__ void fma2(unsigned long long& d, unsigned long long a, unsigned long long b){
    asm("fma.rn.f32x2 %0, %1, %2, %0;" : "+l"(d) : "l"(a), "l"(b));
}
__device__ __forceinline__ unsigned long long pk2(float lo, float hi){
    unsigned long long r; asm("mov.b64 %0,{%1,%2};" : "=l"(r) : "f"(lo), "f"(hi)); return r;
}
__device__ __forceinline__ float upk_sum(unsigned long long v){
    float lo, hi; asm("mov.b64 {%0,%1},%2;" : "=f"(lo), "=f"(hi) : "l"(v)); return lo+hi;
}

// ================= setup =================
__global__ void k_zero(const int* __restrict__ x, const float* __restrict__ emb) {
    int t = blockIdx.x*256 + threadIdx.x;     // 0..24575
    if (t < Nn*NW){ d_abits[t]=0u; d_nbits[t]=0u; }
    if (t < Nn) d_cnt[t]=0;
    if (t < Hh){ d_S1[t]=0.f; d_S2[t]=0.f; }
    if (t == 0) d_cntM=0;
    d_h[t] = emb[x[t>>5]*Hh + (t&31)];
}

__global__ void k_scatter(const int* __restrict__ ei, const int* __restrict__ pos) {
    int t = blockIdx.x*256 + threadIdx.x;
    int u = ei[t], v = ei[Ee+t];
    atomicOr(&d_abits[u*NW+(v>>5)], 1u<<(v&31));
    atomicAdd(&d_cnt[u], 1);
    if (t < Pp){
        int a=pos[2*t], b=pos[2*t+1];
        atomicOr(&d_nbits[a*NW+(b>>5)], 1u<<(b&31));
        atomicOr(&d_nbits[b*NW+(a>>5)], 1u<<(a&31));
    }
}

// single block: CSR scan + dinv
__global__ void k_scan() {
    __shared__ int wsum[8];
    int tid = threadIdx.x, w = tid>>5, lane = tid&31;
    int lo = tid*3;
    int c0=d_cnt[lo], c1=d_cnt[lo+1], c2=d_cnt[lo+2];
    int s = c0+c1+c2, sc = s;
    #pragma unroll
    for (int o=1;o<32;o<<=1){ int t2=__shfl_up_sync(0xffffffffu,sc,o); if (lane>=o) sc+=t2; }
    if (lane==31) wsum[w]=sc;
    __syncthreads();
    if (w==0){                                    // ALL 32 lanes participate
        int v = (lane<8) ? wsum[lane] : 0;
        int p = v;
        #pragma unroll
        for (int o=1;o<8;o<<=1){ int t2=__shfl_up_sync(0xffffffffu,p,o); if (lane>=o) p+=t2; }
        if (lane<8) wsum[lane]=p-v;
    }
    __syncthreads();
    int base = wsum[w] + sc - s;
    d_base[lo]=base;        d_fillc[lo]=base;
    d_base[lo+1]=base+c0;   d_fillc[lo+1]=base+c0;
    d_base[lo+2]=base+c0+c1;d_fillc[lo+2]=base+c0+c1;
    if (tid==255) d_base[Nn]=Ee;
    // dinv
    for (int r=tid; r<Nn; r+=256){
        int p=0;
        #pragma unroll
        for (int c=0;c<NW;c++) p += __popc(d_abits[r*NW+c]);
        d_dinv[r] = rsqrtf((float)p + 1.0f);
    }
}

__global__ void k_fill(const int* __restrict__ ei) {
    int t = blockIdx.x*256 + threadIdx.x;
    int u = ei[t], v = ei[Ee+t];
    int s = atomicAdd(&d_fillc[u], 1);
    d_col[s]=v; d_cu[s]=u;
}

// ================= per-row pair build (768 blocks) =================
__global__ void __launch_bounds__(256) k_build() {
    __shared__ int scnt[Nn];
    __shared__ int scur[Nn];
    __shared__ int wsum[8];
    int tid = threadIdx.x, w = tid>>5, lane = tid&31;
    int i = blockIdx.x;
    for (int t=tid; t<Nn; t+=256) scnt[t]=0;
    __syncthreads();
    int es = d_base[i], ee = d_base[i+1];
    // pass 1: counts
    for (int e=es+w; e<ee; e+=8){
        int k = d_col[e];
        int fs = d_base[k], fe = d_base[k+1];
        for (int f=fs+lane; f<fe; f+=32) atomicAdd(&scnt[d_col[f]], 1);
    }
    __syncthreads();
    // scan 768 counters (3 per thread)
    int lo = tid*3;
    int c0=scnt[lo], c1=scnt[lo+1], c2=scnt[lo+2];
    int s = c0+c1+c2, sc = s;
    #pragma unroll
    for (int o=1;o<32;o<<=1){ int t2=__shfl_up_sync(0xffffffffu,sc,o); if (lane>=o) sc+=t2; }
    if (lane==31) wsum[w]=sc;
    __syncthreads();
    if (w==0){                                    // ALL 32 lanes participate
        int v = (lane<8) ? wsum[lane] : 0;
        int p = v;
        #pragma unroll
        for (int o=1;o<8;o<<=1){ int t2=__shfl_up_sync(0xffffffffu,p,o); if (lane>=o) p+=t2; }
        if (lane<8) wsum[lane]=p-v;
    }
    __syncthreads();
    int b0 = wsum[w] + sc - s;
    scur[lo]=b0; scur[lo+1]=b0+c0; scur[lo+2]=b0+c0+c1;
    d_ijstart[i*Nn+lo]  =b0;        d_ijend[i*Nn+lo]  =b0+c0;
    d_ijstart[i*Nn+lo+1]=b0+c0;     d_ijend[i*Nn+lo+1]=b0+c0+c1;
    d_ijstart[i*Nn+lo+2]=b0+c0+c1;  d_ijend[i*Nn+lo+2]=b0+c0+c1+c2;
    __syncthreads();
    // pass 2: fill
    int* prow = d_pairs + i*BUD;
    for (int e=es+w; e<ee; e+=8){
        int k = d_col[e];
        int fs = d_base[k], fe = d_base[k+1];
        for (int f=fs+lane; f<fe; f+=32){
            int slot = atomicAdd(&scur[d_col[f]], 1);
            prow[slot] = e | (f<<16);
        }
    }
}

// ================= GCN =================
// hT = dinv * (h @ W0)   (warp per row)
__global__ void k_hw0(const float* __restrict__ gcnW) {
    int w = threadIdx.x>>5, lane = threadIdx.x&31;
    int r = blockIdx.x*8 + w;
    float hv = d_h[r*Hh+lane];
    float acc = 0.f;
    #pragma unroll
    for (int k=0;k<32;k++) acc += __shfl_sync(0xffffffffu,hv,k) * gcnW[k*Hh+lane];
    d_hT[r*Hh+lane] = d_dinv[r]*acc;
}

// agg (half-row per warp, 192 blocks): d_hP = dinv*(sum+self)+b ; block partials
template<int L>
__global__ void k_agg(const float* __restrict__ gcnb) {
    __shared__ float sAg[8][32];
    __shared__ float red1[4][32], red2[4][32];
    int w = threadIdx.x>>5, lane = threadIdx.x&31;
    int r = blockIdx.x*4 + (w>>1);
    int half = w&1;
    float aggv = 0.f;
    #pragma unroll 1
    for (int wd=half*12; wd<half*12+12; wd++){
        unsigned m = d_abits[r*NW+wd];
        int jb = wd*32;
        while (m){ int b=__ffs(m)-1; m&=m-1; aggv += d_hT[(jb+b)*Hh+lane]; }
    }
    sAg[w][lane]=aggv;
    __syncthreads();
    if (half==0){
        float tot = sAg[w][lane] + sAg[w+1][lane];
        float v = d_dinv[r]*(tot + d_hT[r*Hh+lane]) + gcnb[L*Hh+lane];
        d_hP[r*Hh+lane]=v;
        red1[w>>1][lane]=v; red2[w>>1][lane]=v*v;
    }
    __syncthreads();
    if (w==0){
        float s1=0.f, s2=0.f;
        #pragma unroll
        for (int q=0;q<4;q++){ s1+=red1[q][lane]; s2+=red2[q][lane]; }
        d_p1[blockIdx.x*32+lane]=s1; d_p2[blockIdx.x*32+lane]=s2;
    }
}

// finalize norm0 + write h + hT = dinv*(h @ W1)
__global__ void k_hw1(const float* __restrict__ gcnW) {
    int w = threadIdx.x>>5, lane = threadIdx.x&31;
    int r = blockIdx.x*8 + w;
    float s1=0.f, s2=0.f;
    #pragma unroll 4
    for (int b=0;b<NAGG;b++){ s1+=d_p1[b*32+lane]; s2+=d_p2[b*32+lane]; }
    float mean = s1/(float)Nn;
    float inv  = rsqrtf(s2/(float)Nn - mean*mean + 1e-5f);
    float hv = fmaxf((d_hP[r*Hh+lane]-mean)*inv, 0.f);
    float acc = 0.f;
    #pragma unroll
    for (int k=0;k<32;k++) acc += __shfl_sync(0xffffffffu,hv,k) * gcnW[Hh*Hh + k*Hh+lane];
    d_hT[r*Hh+lane] = d_dinv[r]*acc;
}

// finalize norm1 -> d_h
__global__ void k_norm1() {
    int w = threadIdx.x>>5, lane = threadIdx.x&31;
    int r = blockIdx.x*8 + w;
    float s1=0.f, s2=0.f;
    #pragma unroll 4
    for (int b=0;b<NAGG;b++){ s1+=d_p1[b*32+lane]; s2+=d_p2[b*32+lane]; }
    float mean = s1/(float)Nn;
    float inv  = rsqrtf(s2/(float)Nn - mean*mean + 1e-5f);
    d_h[r*Hh+lane] = fmaxf((d_hP[r*Hh+lane]-mean)*inv, 0.f);
}

// ================= edge MLPs (warp per CSR slot) =================
__global__ void k_mlp(const float* __restrict__ W1, const float* __restrict__ b1,
                      const float* __restrict__ W2, const float* __restrict__ b2) {
    int w = threadIdx.x>>5, lane = threadIdx.x&31;
    int s = blockIdx.x*8 + w;
    int u = d_cu[s], v = d_col[s];
    float hu = d_h[u*Hh+lane], hv = d_h[v*Hh+lane];
    float x1 = b1[lane], x2 = b2[lane];
    #pragma unroll
    for (int k=0;k<32;k++){
        float a = __shfl_sync(0xffffffffu,hu,k);
        float b = __shfl_sync(0xffffffffu,hv,k);
        x1 += a*W1[k*Hh+lane] + b*W1[(k+32)*Hh+lane];
        x2 += a*W2[k*Hh+lane] + b*W2[(k+32)*Hh+lane];
    }
    d_xe [s*Hh+lane]=fmaxf(x1,0.f);
    d_mul[s*Hh+lane]=fmaxf(x2,0.f);
}

// ================= hot kernel: per-(i,j) C + z + moments =================
// warp handles 32 consecutive j in one row; pipelined gather/dot
__global__ void __launch_bounds__(256,3) k_z(const float* __restrict__ W3,
                                             const float* __restrict__ b3v) {
    __shared__ unsigned long long sW[16*32];   // packed W3 pairs
    __shared__ float sC[8][64];                // double-buffered transpose slot
    __shared__ float sr1[8][32], sr2[8][32];
    __shared__ int src[8];
    int tid = threadIdx.x, w = tid>>5, lane = tid&31;

    // load packed W3 into smem
    #pragma unroll
    for (int f=tid; f<512; f+=256){
        int t = f>>5, ln = f&31;
        sW[f] = pk2(W3[(2*t)*Hh+ln], W3[(2*t+1)*Hh+ln]);
    }
    __syncthreads();

    int wid = blockIdx.x*8 + w;            // 0..18431
    int i = wid/24;
    int wrd = wid - i*24;                  // word index within row
    int ij0 = i*Nn + wrd*32;

    int start = d_ijstart[ij0+lane];
    int end   = d_ijend  [ij0+lane];
    unsigned mA = d_abits[i*NW + wrd];
    unsigned mN = d_nbits[i*NW + wrd];
    unsigned hasP = __ballot_sync(0xffffffffu, end>start);
    unsigned mM = mA | hasP;
    d_maskb[ij0+lane] = (unsigned char)((mM>>lane)&1u);
    int c0 = __popc(mM);

    float s1=0.f, s2=0.f;
    if (mM) {
        const int* prow = d_pairs + i*BUD;
        float w3last = W3[32*Hh+lane];
        float bb = b3v[lane];
        unsigned rem = mM;
        int bcur = __ffs(rem)-1; rem &= rem-1;
        int par = 0;
        {   // prologue gather
            int st=__shfl_sync(0xffffffffu,start,bcur), en=__shfl_sync(0xffffffffu,end,bcur);
            float C=0.f;
            for (int t=st;t<en;t++){
                int p = prow[t];
                C += d_xe[(p&0xFFFF)*Hh+lane] * d_mul[(p>>16)*Hh+lane];
            }
            sC[w][lane]=C; __syncwarp();
        }
        while (true){
            int bnext = -1;
            if (rem){ bnext=__ffs(rem)-1; rem&=rem-1; }
            float Cn = 0.f;
            if (bnext>=0){                              // gather next (overlaps dot below)
                int st=__shfl_sync(0xffffffffu,start,bnext), en=__shfl_sync(0xffffffffu,end,bnext);
                for (int t=st;t<en;t++){
                    int p = prow[t];
                    Cn += d_xe[(p&0xFFFF)*Hh+lane] * d_mul[(p>>16)*Hh+lane];
                }
            }
            // dot for bcur from sC slot 'par'
            const ulonglong2* Cj = (const ulonglong2*)&sC[w][par*32];
            unsigned long long a0=0ull, a1=0ull;
            #pragma unroll
            for (int q=0;q<4;q++){
                ulonglong2 cA = Cj[q];
                ulonglong2 cB = Cj[q+4];
                fma2(a0, cA.x, sW[(2*q)*32+lane]);     fma2(a0, cA.y, sW[(2*q+1)*32+lane]);
                fma2(a1, cB.x, sW[(2*q+8)*32+lane]);   fma2(a1, cB.y, sW[(2*q+9)*32+lane]);
            }
            float acc = bb + upk_sum(a0) + upk_sum(a1) + (((mA>>bcur)&1u) ? w3last : 0.f);
            s1 += acc; s2 += acc*acc;
            if ((mN>>bcur)&1u) d_z[(size_t)(ij0+bcur)*Hh + lane] = acc;
            if (bnext<0) break;
            par ^= 1;
            sC[w][par*32+lane]=Cn; __syncwarp();
            bcur = bnext;
        }
    }
    sr1[w][lane]=s1; sr2[w][lane]=s2; if (lane==0) src[w]=c0;
    __syncthreads();
    if (w==0){
        float a=0.f, b=0.f;
        #pragma unroll
        for (int r=0;r<8;r++){ a+=sr1[r][lane]; b+=sr2[r][lane]; }
        atomicAdd(&d_S1[lane], a);
        atomicAdd(&d_S2[lane], b);
        if (lane==0){ int cc=0; for (int r=0;r<8;r++) cc+=src[r]; atomicAdd(&d_cntM, cc); }
    }
}

// ================= output =================
__global__ void k_pos(const int* __restrict__ pos, const float* __restrict__ linW,
                      const float* __restrict__ linb, float* __restrict__ out) {
    int w = threadIdx.x>>5, lane = threadIdx.x&31;
    int p = blockIdx.x*8 + w;
    float cnt = (float)d_cntM;
    float mean = d_S1[lane]/cnt;
    float inv  = rsqrtf(d_S2[lane]/cnt - mean*mean + 1e-5f);
    int p0 = pos[2*p], p1 = pos[2*p+1];
    float acc = d_h[p0*Hh+lane]*d_h[p1*Hh+lane]*linW[Hh+lane];
    if (d_maskb[p0*Nn+p1]) {
        float z1 = d_z[((size_t)p0*Nn+p1)*Hh+lane];
        float z2 = d_z[((size_t)p1*Nn+p0)*Hh+lane];
        acc += fmaxf((z1-mean)*inv,0.f)*fmaxf((z2-mean)*inv,0.f)*linW[lane];
    }
    for (int o=16;o;o>>=1) acc += __shfl_down_sync(0xffffffffu, acc, o);
    if (lane==0) out[p] = acc + linb[0];
}

// ================= launch =================
extern "C" void kernel_launch(void* const* d_in, const int* in_sizes, int n_in,
                              void* d_out, int out_size) {
    const int*   x    = (const int*)  d_in[0];
    const int*   ei   = (const int*)  d_in[1];
    const int*   pos  = (const int*)  d_in[2];
    const float* emb  = (const float*)d_in[3];
    const float* gcnW = (const float*)d_in[4];
    const float* gcnb = (const float*)d_in[5];
    const float* W1   = (const float*)d_in[6];
    const float* b1   = (const float*)d_in[7];
    const float* W2   = (const float*)d_in[8];
    const float* b2   = (const float*)d_in[9];
    const float* W3   = (const float*)d_in[10];
    const float* b3   = (const float*)d_in[11];
    const float* linW = (const float*)d_in[12];
    const float* linb = (const float*)d_in[13];
    float* out = (float*)d_out;

    k_zero   <<<96, 256>>>(x, emb);
    k_scatter<<<96, 256>>>(ei, pos);
    k_scan   <<<1,  256>>>();
    k_fill   <<<96, 256>>>(ei);
    k_build  <<<Nn, 256>>>();
    k_hw0    <<<96, 256>>>(gcnW);
    k_agg<0> <<<NAGG,256>>>(gcnb);
    k_hw1    <<<96, 256>>>(gcnW);
    k_agg<1> <<<NAGG,256>>>(gcnb);
    k_norm1  <<<96, 256>>>();
    k_mlp    <<<Ee/8,256>>>(W1,b1,W2,b2);
    k_z      <<<Nn*NW/8,256>>>(W3,b3);
    k_pos    <<<Pp/8,256>>>(pos, linW, linb, out);
}

// round 7
// speedup vs baseline: 1.8706x; 1.3211x over previous
#include <cuda_runtime.h>

#define Nn 768
#define Hh 32
#define Ee 24576
#define Pp 4096
#define NW 24              // 768/32 bitmask words per row
#define BUD 6144           // per-row pair budget
#define NAGG 192

// ---------------- scratch ----------------
__device__ unsigned d_abits[Nn*NW];
__device__ unsigned d_nbits[Nn*NW];
__device__ unsigned char d_maskb[Nn*Nn];
__device__ float d_dinv[Nn];
__device__ float d_h [Nn*Hh];
__device__ float d_hT[Nn*Hh];
__device__ float d_hP[Nn*Hh];
__device__ int   d_cnt [Nn];
__device__ int   d_base[Nn+1];
__device__ int   d_fillc[Nn];
__device__ int   d_col[Ee];
__device__ int   d_cu [Ee];
__device__ int   d_ijstart[Nn*Nn];     // local (within-row) segment starts
__device__ int   d_ijend  [Nn*Nn];
__device__ int2  d_pair2[Nn*BUD];      // {e | f<<16, j&31}
__device__ float d_xe [Ee*Hh];
__device__ float d_mul[Ee*Hh];
__device__ float d_z  [(size_t)Nn*Nn*Hh];
__device__ float d_p1[NAGG*Hh], d_p2[NAGG*Hh];
__device__ float d_S1[Hh], d_S2[Hh];
__device__ int   d_cntM;

// ---------------- f32x2 helpers ----------------
__device__ __forceinline__ void fma2(unsigned long long& d, unsigned long long a, unsigned long long b){
    asm("fma.rn.f32x2 %0, %1, %2, %0;" : "+l"(d) : "l"(a), "l"(b));
}
__device__ __forceinline__ unsigned long long pk2(float lo, float hi){
    unsigned long long r; asm("mov.b64 %0,{%1,%2};" : "=l"(r) : "f"(lo), "f"(hi)); return r;
}
__device__ __forceinline__ float upk_sum(unsigned long long v){
    float lo, hi; asm("mov.b64 {%0,%1},%2;" : "=f"(lo), "=f"(hi) : "l"(v)); return lo+hi;
}

// ================= setup =================
__global__ void k_zero(const int* __restrict__ x, const float* __restrict__ emb) {
    int t = blockIdx.x*256 + threadIdx.x;     // 0..24575
    if (t < Nn*NW){ d_abits[t]=0u; d_nbits[t]=0u; }
    if (t < Nn) d_cnt[t]=0;
    if (t < Hh){ d_S1[t]=0.f; d_S2[t]=0.f; }
    if (t == 0) d_cntM=0;
    d_h[t] = emb[x[t>>5]*Hh + (t&31)];
}

__global__ void k_scatter(const int* __restrict__ ei, const int* __restrict__ pos) {
    int t = blockIdx.x*256 + threadIdx.x;
    int u = ei[t], v = ei[Ee+t];
    atomicOr(&d_abits[u*NW+(v>>5)], 1u<<(v&31));
    atomicAdd(&d_cnt[u], 1);
    if (t < Pp){
        int a=pos[2*t], b=pos[2*t+1];
        atomicOr(&d_nbits[a*NW+(b>>5)], 1u<<(b&31));
        atomicOr(&d_nbits[b*NW+(a>>5)], 1u<<(a&31));
    }
}

// single block: CSR scan + dinv
__global__ void k_scan() {
    __shared__ int wsum[8];
    int tid = threadIdx.x, w = tid>>5, lane = tid&31;
    int lo = tid*3;
    int c0=d_cnt[lo], c1=d_cnt[lo+1], c2=d_cnt[lo+2];
    int s = c0+c1+c2, sc = s;
    #pragma unroll
    for (int o=1;o<32;o<<=1){ int t2=__shfl_up_sync(0xffffffffu,sc,o); if (lane>=o) sc+=t2; }
    if (lane==31) wsum[w]=sc;
    __syncthreads();
    if (w==0){                                    // all 32 lanes participate
        int v = (lane<8) ? wsum[lane] : 0;
        int p = v;
        #pragma unroll
        for (int o=1;o<8;o<<=1){ int t2=__shfl_up_sync(0xffffffffu,p,o); if (lane>=o) p+=t2; }
        if (lane<8) wsum[lane]=p-v;
    }
    __syncthreads();
    int base = wsum[w] + sc - s;
    d_base[lo]=base;        d_fillc[lo]=base;
    d_base[lo+1]=base+c0;   d_fillc[lo+1]=base+c0;
    d_base[lo+2]=base+c0+c1;d_fillc[lo+2]=base+c0+c1;
    if (tid==255) d_base[Nn]=Ee;
    // dinv
    for (int r=tid; r<Nn; r+=256){
        int p=0;
        #pragma unroll
        for (int c=0;c<NW;c++) p += __popc(d_abits[r*NW+c]);
        d_dinv[r] = rsqrtf((float)p + 1.0f);
    }
}

__global__ void k_fill(const int* __restrict__ ei) {
    int t = blockIdx.x*256 + threadIdx.x;
    int u = ei[t], v = ei[Ee+t];
    int s = atomicAdd(&d_fillc[u], 1);
    d_col[s]=v; d_cu[s]=u;
}

// ================= per-row pair build (768 blocks) =================
__global__ void __launch_bounds__(256) k_build() {
    __shared__ int scnt[Nn];
    __shared__ int scur[Nn];
    __shared__ int wsum[8];
    int tid = threadIdx.x, w = tid>>5, lane = tid&31;
    int i = blockIdx.x;
    for (int t=tid; t<Nn; t+=256) scnt[t]=0;
    __syncthreads();
    int es = d_base[i], ee = d_base[i+1];
    // pass 1: counts
    for (int e=es+w; e<ee; e+=8){
        int k = d_col[e];
        int fs = d_base[k], fe = d_base[k+1];
        for (int f=fs+lane; f<fe; f+=32) atomicAdd(&scnt[d_col[f]], 1);
    }
    __syncthreads();
    // scan 768 counters (3 per thread)
    int lo = tid*3;
    int c0=scnt[lo], c1=scnt[lo+1], c2=scnt[lo+2];
    int s = c0+c1+c2, sc = s;
    #pragma unroll
    for (int o=1;o<32;o<<=1){ int t2=__shfl_up_sync(0xffffffffu,sc,o); if (lane>=o) sc+=t2; }
    if (lane==31) wsum[w]=sc;
    __syncthreads();
    if (w==0){                                    // all 32 lanes participate
        int v = (lane<8) ? wsum[lane] : 0;
        int p = v;
        #pragma unroll
        for (int o=1;o<8;o<<=1){ int t2=__shfl_up_sync(0xffffffffu,p,o); if (lane>=o) p+=t2; }
        if (lane<8) wsum[lane]=p-v;
    }
    __syncthreads();
    int b0 = wsum[w] + sc - s;
    scur[lo]=b0; scur[lo+1]=b0+c0; scur[lo+2]=b0+c0+c1;
    d_ijstart[i*Nn+lo]  =b0;        d_ijend[i*Nn+lo]  =b0+c0;
    d_ijstart[i*Nn+lo+1]=b0+c0;     d_ijend[i*Nn+lo+1]=b0+c0+c1;
    d_ijstart[i*Nn+lo+2]=b0+c0+c1;  d_ijend[i*Nn+lo+2]=b0+c0+c1+c2;
    __syncthreads();
    // pass 2: fill (int2: descriptor + local j)
    int2* prow = d_pair2 + i*BUD;
    for (int e=es+w; e<ee; e+=8){
        int k = d_col[e];
        int fs = d_base[k], fe = d_base[k+1];
        for (int f=fs+lane; f<fe; f+=32){
            int j = d_col[f];
            int slot = atomicAdd(&scur[j], 1);
            prow[slot] = make_int2(e | (f<<16), j & 31);
        }
    }
}

// ================= GCN =================
__global__ void k_hw0(const float* __restrict__ gcnW) {
    int w = threadIdx.x>>5, lane = threadIdx.x&31;
    int r = blockIdx.x*8 + w;
    float hv = d_h[r*Hh+lane];
    float acc = 0.f;
    #pragma unroll
    for (int k=0;k<32;k++) acc += __shfl_sync(0xffffffffu,hv,k) * gcnW[k*Hh+lane];
    d_hT[r*Hh+lane] = d_dinv[r]*acc;
}

template<int L>
__global__ void k_agg(const float* __restrict__ gcnb) {
    __shared__ float sAg[8][32];
    __shared__ float red1[4][32], red2[4][32];
    int w = threadIdx.x>>5, lane = threadIdx.x&31;
    int r = blockIdx.x*4 + (w>>1);
    int half = w&1;
    float aggv = 0.f;
    #pragma unroll 1
    for (int wd=half*12; wd<half*12+12; wd++){
        unsigned m = d_abits[r*NW+wd];
        int jb = wd*32;
        while (m){ int b=__ffs(m)-1; m&=m-1; aggv += d_hT[(jb+b)*Hh+lane]; }
    }
    sAg[w][lane]=aggv;
    __syncthreads();
    if (half==0){
        float tot = sAg[w][lane] + sAg[w+1][lane];
        float v = d_dinv[r]*(tot + d_hT[r*Hh+lane]) + gcnb[L*Hh+lane];
        d_hP[r*Hh+lane]=v;
        red1[w>>1][lane]=v; red2[w>>1][lane]=v*v;
    }
    __syncthreads();
    if (w==0){
        float s1=0.f, s2=0.f;
        #pragma unroll
        for (int q=0;q<4;q++){ s1+=red1[q][lane]; s2+=red2[q][lane]; }
        d_p1[blockIdx.x*32+lane]=s1; d_p2[blockIdx.x*32+lane]=s2;
    }
}

__global__ void k_hw1(const float* __restrict__ gcnW) {
    int w = threadIdx.x>>5, lane = threadIdx.x&31;
    int r = blockIdx.x*8 + w;
    float s1=0.f, s2=0.f;
    #pragma unroll 4
    for (int b=0;b<NAGG;b++){ s1+=d_p1[b*32+lane]; s2+=d_p2[b*32+lane]; }
    float mean = s1/(float)Nn;
    float inv  = rsqrtf(s2/(float)Nn - mean*mean + 1e-5f);
    float hv = fmaxf((d_hP[r*Hh+lane]-mean)*inv, 0.f);
    float acc = 0.f;
    #pragma unroll
    for (int k=0;k<32;k++) acc += __shfl_sync(0xffffffffu,hv,k) * gcnW[Hh*Hh + k*Hh+lane];
    d_hT[r*Hh+lane] = d_dinv[r]*acc;
}

__global__ void k_norm1() {
    int w = threadIdx.x>>5, lane = threadIdx.x&31;
    int r = blockIdx.x*8 + w;
    float s1=0.f, s2=0.f;
    #pragma unroll 4
    for (int b=0;b<NAGG;b++){ s1+=d_p1[b*32+lane]; s2+=d_p2[b*32+lane]; }
    float mean = s1/(float)Nn;
    float inv  = rsqrtf(s2/(float)Nn - mean*mean + 1e-5f);
    d_h[r*Hh+lane] = fmaxf((d_hP[r*Hh+lane]-mean)*inv, 0.f);
}

// ================= edge MLPs (warp per CSR slot) =================
__global__ void k_mlp(const float* __restrict__ W1, const float* __restrict__ b1,
                      const float* __restrict__ W2, const float* __restrict__ b2) {
    int w = threadIdx.x>>5, lane = threadIdx.x&31;
    int s = blockIdx.x*8 + w;
    int u = d_cu[s], v = d_col[s];
    float hu = d_h[u*Hh+lane], hv = d_h[v*Hh+lane];
    float x1 = b1[lane], x2 = b2[lane];
    #pragma unroll
    for (int k=0;k<32;k++){
        float a = __shfl_sync(0xffffffffu,hu,k);
        float b = __shfl_sync(0xffffffffu,hv,k);
        x1 += a*W1[k*Hh+lane] + b*W1[(k+32)*Hh+lane];
        x2 += a*W2[k*Hh+lane] + b*W2[(k+32)*Hh+lane];
    }
    d_xe [s*Hh+lane]=fmaxf(x1,0.f);
    d_mul[s*Hh+lane]=fmaxf(x2,0.f);
}

// ================= hot kernel: two-phase flat-stream C + z + moments =================
// warp handles 32 consecutive j in one row; pair segments for the window are
// CONTIGUOUS in d_pair2 -> one flat stream with 4-deep descriptor prefetch.
__global__ void __launch_bounds__(256,4) k_z(const float* __restrict__ W3,
                                             const float* __restrict__ b3v) {
    __shared__ unsigned long long sW[512];     // packed W3 pairs
    __shared__ float sC[8][1024];              // per-warp 32x32 C buffer
    __shared__ float sr1[8][32], sr2[8][32];
    __shared__ int src[8];
    int tid = threadIdx.x, w = tid>>5, lane = tid&31;

    #pragma unroll
    for (int f=tid; f<512; f+=256){
        int t = f>>5, ln = f&31;
        sW[f] = pk2(W3[(2*t)*Hh+ln], W3[(2*t+1)*Hh+ln]);
    }
    __syncthreads();

    int wid = blockIdx.x*8 + w;            // 0..18431
    int i = wid/24;
    int wrd = wid - i*24;
    int ij0 = i*Nn + wrd*32;

    int start = d_ijstart[ij0+lane];
    int end   = d_ijend  [ij0+lane];
    unsigned mA = d_abits[i*NW + wrd];
    unsigned mN = d_nbits[i*NW + wrd];
    unsigned hasP = __ballot_sync(0xffffffffu, end>start);
    unsigned mM = mA | hasP;
    d_maskb[ij0+lane] = (unsigned char)((mM>>lane)&1u);
    int c0 = __popc(mM);

    float s1=0.f, s2=0.f;
    if (mM) {
        float* sCw = sC[w];
        // zero own buffer
        {
            float4 z4 = make_float4(0.f,0.f,0.f,0.f);
            float4* p4 = (float4*)sCw;
            #pragma unroll
            for (int t=lane; t<256; t+=32) p4[t]=z4;
        }
        __syncwarp();

        // ---- phase A: flat pair stream, groups of 4 with descriptor prefetch ----
        int winS = __shfl_sync(0xffffffffu, start, 0);
        int winE = __shfl_sync(0xffffffffu, end, 31);
        const int2* prow = d_pair2 + i*BUD;
        int t = winS;
        int2 q0,q1,q2,q3;
        bool have = (t+4 <= winE);
        if (have){ q0=prow[t]; q1=prow[t+1]; q2=prow[t+2]; q3=prow[t+3]; }
        while (have){
            int tn = t+4;
            int2 n0,n1,n2,n3;
            bool haven = (tn+4 <= winE);
            if (haven){ n0=prow[tn]; n1=prow[tn+1]; n2=prow[tn+2]; n3=prow[tn+3]; }
            float a0 = d_xe[(q0.x&0xFFFF)*Hh+lane], m0 = d_mul[((unsigned)q0.x>>16)*Hh+lane];
            float a1 = d_xe[(q1.x&0xFFFF)*Hh+lane], m1 = d_mul[((unsigned)q1.x>>16)*Hh+lane];
            float a2 = d_xe[(q2.x&0xFFFF)*Hh+lane], m2 = d_mul[((unsigned)q2.x>>16)*Hh+lane];
            float a3 = d_xe[(q3.x&0xFFFF)*Hh+lane], m3 = d_mul[((unsigned)q3.x>>16)*Hh+lane];
            sCw[q0.y*Hh+lane] += a0*m0;
            sCw[q1.y*Hh+lane] += a1*m1;
            sCw[q2.y*Hh+lane] += a2*m2;
            sCw[q3.y*Hh+lane] += a3*m3;
            q0=n0; q1=n1; q2=n2; q3=n3;
            t = tn; have = haven;
        }
        for (; t<winE; t++){
            int2 q = prow[t];
            sCw[q.y*Hh+lane] += d_xe[(q.x&0xFFFF)*Hh+lane] * d_mul[((unsigned)q.x>>16)*Hh+lane];
        }
        __syncwarp();

        // ---- phase B: z = C@W3 + af*W3[32] + b3 ; moments ; sparse z store ----
        float w3last = W3[32*Hh+lane];
        float bb = b3v[lane];
        unsigned rem = mM;
        while (rem){
            int b = __ffs(rem)-1; rem &= rem-1;
            const ulonglong2* Cj = (const ulonglong2*)(sCw + b*Hh);
            unsigned long long a0=0ull, a1=0ull;
            #pragma unroll
            for (int q=0;q<4;q++){
                ulonglong2 cA = Cj[q];
                ulonglong2 cB = Cj[q+4];
                fma2(a0, cA.x, sW[(2*q)*32+lane]);     fma2(a0, cA.y, sW[(2*q+1)*32+lane]);
                fma2(a1, cB.x, sW[(2*q+8)*32+lane]);   fma2(a1, cB.y, sW[(2*q+9)*32+lane]);
            }
            float acc = bb + upk_sum(a0) + upk_sum(a1) + (((mA>>b)&1u) ? w3last : 0.f);
            s1 += acc; s2 += acc*acc;
            if ((mN>>b)&1u) d_z[(size_t)(ij0+b)*Hh + lane] = acc;
        }
    }
    sr1[w][lane]=s1; sr2[w][lane]=s2; if (lane==0) src[w]=c0;
    __syncthreads();
    if (w==0){
        float a=0.f, b=0.f;
        #pragma unroll
        for (int r=0;r<8;r++){ a+=sr1[r][lane]; b+=sr2[r][lane]; }
        atomicAdd(&d_S1[lane], a);
        atomicAdd(&d_S2[lane], b);
        if (lane==0){ int cc=0; for (int r=0;r<8;r++) cc+=src[r]; atomicAdd(&d_cntM, cc); }
    }
}

// ================= output =================
__global__ void k_pos(const int* __restrict__ pos, const float* __restrict__ linW,
                      const float* __restrict__ linb, float* __restrict__ out) {
    int w = threadIdx.x>>5, lane = threadIdx.x&31;
    int p = blockIdx.x*8 + w;
    float cnt = (float)d_cntM;
    float mean = d_S1[lane]/cnt;
    float inv  = rsqrtf(d_S2[lane]/cnt - mean*mean + 1e-5f);
    int p0 = pos[2*p], p1 = pos[2*p+1];
    float acc = d_h[p0*Hh+lane]*d_h[p1*Hh+lane]*linW[Hh+lane];
    if (d_maskb[p0*Nn+p1]) {
        float z1 = d_z[((size_t)p0*Nn+p1)*Hh+lane];
        float z2 = d_z[((size_t)p1*Nn+p0)*Hh+lane];
        acc += fmaxf((z1-mean)*inv,0.f)*fmaxf((z2-mean)*inv,0.f)*linW[lane];
    }
    for (int o=16;o;o>>=1) acc += __shfl_down_sync(0xffffffffu, acc, o);
    if (lane==0) out[p] = acc + linb[0];
}

// ================= launch =================
extern "C" void kernel_launch(void* const* d_in, const int* in_sizes, int n_in,
                              void* d_out, int out_size) {
    const int*   x    = (const int*)  d_in[0];
    const int*   ei   = (const int*)  d_in[1];
    const int*   pos  = (const int*)  d_in[2];
    const float* emb  = (const float*)d_in[3];
    const float* gcnW = (const float*)d_in[4];
    const float* gcnb = (const float*)d_in[5];
    const float* W1   = (const float*)d_in[6];
    const float* b1   = (const float*)d_in[7];
    const float* W2   = (const float*)d_in[8];
    const float* b2   = (const float*)d_in[9];
    const float* W3   = (const float*)d_in[10];
    const float* b3   = (const float*)d_in[11];
    const float* linW = (const float*)d_in[12];
    const float* linb = (const float*)d_in[13];
    float* out = (float*)d_out;

    k_zero   <<<96, 256>>>(x, emb);
    k_scatter<<<96, 256>>>(ei, pos);
    k_scan   <<<1,  256>>>();
    k_fill   <<<96, 256>>>(ei);
    k_build  <<<Nn, 256>>>();
    k_hw0    <<<96, 256>>>(gcnW);
    k_agg<0> <<<NAGG,256>>>(gcnb);
    k_hw1    <<<96, 256>>>(gcnW);
    k_agg<1> <<<NAGG,256>>>(gcnb);
    k_norm1  <<<96, 256>>>();
    k_mlp    <<<Ee/8,256>>>(W1,b1,W2,b2);
    k_z      <<<Nn*NW/8,256>>>(W3,b3);
    k_pos    <<<Pp/8,256>>>(pos, linW, linb, out);
}

// round 8
// speedup vs baseline: 1.9180x; 1.0253x over previous
#include <cuda_runtime.h>

#define Nn 768
#define Hh 32
#define Ee 24576
#define Pp 4096
#define NW 24              // 768/32 bitmask words per row
#define STR 96             // fixed CSR stride per row (max degree budget)
#define BUD 6144           // per-row pair budget
#define NAGG 192

// ---------------- scratch ----------------
__device__ unsigned d_abits[Nn*NW];
__device__ unsigned d_nbits[Nn*NW];
__device__ unsigned char d_maskb[Nn*Nn];
__device__ float d_dinv[Nn];
__device__ float d_h [Nn*Hh];
__device__ float d_hT[Nn*Hh];
__device__ float d_hP[Nn*Hh];
__device__ int   d_cnt [Nn];
__device__ int   d_col[Nn*STR];
__device__ int   d_ijstart[Nn*Nn];     // local (within-row) pair-segment starts
__device__ int   d_ijend  [Nn*Nn];
__device__ int   d_pair1[Nn*BUD];      // f | e_local<<17 | j_local<<24
__device__ float d_xe [Nn*STR*Hh];
__device__ float d_mul[Nn*STR*Hh];
__device__ float d_z  [(size_t)Nn*Nn*Hh];
__device__ float d_p1[NAGG*Hh], d_p2[NAGG*Hh];
__device__ float d_S1[Hh], d_S2[Hh];
__device__ int   d_cntM;

// ---------------- f32x2 helpers ----------------
__device__ __forceinline__ void fma2(unsigned long long& d, unsigned long long a, unsigned long long b){
    asm("fma.rn.f32x2 %0, %1, %2, %0;" : "+l"(d) : "l"(a), "l"(b));
}
__device__ __forceinline__ unsigned long long pk2(float lo, float hi){
    unsigned long long r; asm("mov.b64 %0,{%1,%2};" : "=l"(r) : "f"(lo), "f"(hi)); return r;
}
__device__ __forceinline__ float upk_sum(unsigned long long v){
    float lo, hi; asm("mov.b64 {%0,%1},%2;" : "=f"(lo), "=f"(hi) : "l"(v)); return lo+hi;
}

// ================= setup =================
__global__ void k_zero(const int* __restrict__ x, const float* __restrict__ emb) {
    int t = blockIdx.x*256 + threadIdx.x;     // 0..24575
    if (t < Nn*NW){ d_abits[t]=0u; d_nbits[t]=0u; }
    if (t < Nn) d_cnt[t]=0;
    if (t < Hh){ d_S1[t]=0.f; d_S2[t]=0.f; }
    if (t == 0) d_cntM=0;
    d_h[t] = emb[x[t>>5]*Hh + (t&31)];
}

// scatter bits + direct fixed-stride CSR fill
__global__ void k_sf(const int* __restrict__ ei, const int* __restrict__ pos) {
    int t = blockIdx.x*256 + threadIdx.x;
    int u = ei[t], v = ei[Ee+t];
    atomicOr(&d_abits[u*NW+(v>>5)], 1u<<(v&31));
    int slot = atomicAdd(&d_cnt[u], 1);
    d_col[u*STR+slot] = v;
    if (t < Pp){
        int a=pos[2*t], b=pos[2*t+1];
        atomicOr(&d_nbits[a*NW+(b>>5)], 1u<<(b&31));
        atomicOr(&d_nbits[b*NW+(a>>5)], 1u<<(a&31));
    }
}

// ================= per-row pair build (768 blocks) =================
__global__ void __launch_bounds__(256) k_build() {
    __shared__ int scnt[Nn];
    __shared__ int scur[Nn];
    __shared__ int wsum[8];
    int tid = threadIdx.x, w = tid>>5, lane = tid&31;
    int i = blockIdx.x;
    for (int t=tid; t<Nn; t+=256) scnt[t]=0;
    __syncthreads();
    int es = i*STR, deg = d_cnt[i];
    // pass 1: counts
    for (int e=w; e<deg; e+=8){
        int k = d_col[es+e];
        int fk = k*STR, dk = d_cnt[k];
        for (int f=lane; f<dk; f+=32) atomicAdd(&scnt[d_col[fk+f]], 1);
    }
    __syncthreads();
    // scan 768 counters (3 per thread)
    int lo = tid*3;
    int c0=scnt[lo], c1=scnt[lo+1], c2=scnt[lo+2];
    int s = c0+c1+c2, sc = s;
    #pragma unroll
    for (int o=1;o<32;o<<=1){ int t2=__shfl_up_sync(0xffffffffu,sc,o); if (lane>=o) sc+=t2; }
    if (lane==31) wsum[w]=sc;
    __syncthreads();
    if (w==0){                                    // all 32 lanes participate
        int v = (lane<8) ? wsum[lane] : 0;
        int p = v;
        #pragma unroll
        for (int o=1;o<8;o<<=1){ int t2=__shfl_up_sync(0xffffffffu,p,o); if (lane>=o) p+=t2; }
        if (lane<8) wsum[lane]=p-v;
    }
    __syncthreads();
    int b0 = wsum[w] + sc - s;
    scur[lo]=b0; scur[lo+1]=b0+c0; scur[lo+2]=b0+c0+c1;
    d_ijstart[i*Nn+lo]  =b0;        d_ijend[i*Nn+lo]  =b0+c0;
    d_ijstart[i*Nn+lo+1]=b0+c0;     d_ijend[i*Nn+lo+1]=b0+c0+c1;
    d_ijstart[i*Nn+lo+2]=b0+c0+c1;  d_ijend[i*Nn+lo+2]=b0+c0+c1+c2;
    __syncthreads();
    // pass 2: fill single-int descriptors
    int* prow = d_pair1 + i*BUD;
    for (int e=w; e<deg; e+=8){
        int k = d_col[es+e];
        int fk = k*STR, dk = d_cnt[k];
        for (int f=lane; f<dk; f+=32){
            int j = d_col[fk+f];
            int slot = atomicAdd(&scur[j], 1);
            prow[slot] = (fk+f) | (e<<17) | ((j&31)<<24);
        }
    }
}

// ================= GCN =================
// dinv (inline) + hT = dinv * (h @ W0)   (warp per row)
__global__ void k_hw0(const float* __restrict__ gcnW) {
    int w = threadIdx.x>>5, lane = threadIdx.x&31;
    int r = blockIdx.x*8 + w;
    int s = (lane<NW) ? __popc(d_abits[r*NW+lane]) : 0;
    #pragma unroll
    for (int o=16;o;o>>=1) s += __shfl_xor_sync(0xffffffffu, s, o);
    float dv = rsqrtf((float)s + 1.0f);
    if (lane==0) d_dinv[r] = dv;
    float hv = d_h[r*Hh+lane];
    float acc = 0.f;
    #pragma unroll
    for (int k=0;k<32;k++) acc += __shfl_sync(0xffffffffu,hv,k) * gcnW[k*Hh+lane];
    d_hT[r*Hh+lane] = dv*acc;
}

template<int L>
__global__ void k_agg(const float* __restrict__ gcnb) {
    __shared__ float sAg[8][32];
    __shared__ float red1[4][32], red2[4][32];
    int w = threadIdx.x>>5, lane = threadIdx.x&31;
    int r = blockIdx.x*4 + (w>>1);
    int half = w&1;
    float aggv = 0.f;
    #pragma unroll 1
    for (int wd=half*12; wd<half*12+12; wd++){
        unsigned m = d_abits[r*NW+wd];
        int jb = wd*32;
        while (m){ int b=__ffs(m)-1; m&=m-1; aggv += d_hT[(jb+b)*Hh+lane]; }
    }
    sAg[w][lane]=aggv;
    __syncthreads();
    if (half==0){
        float tot = sAg[w][lane] + sAg[w+1][lane];
        float v = d_dinv[r]*(tot + d_hT[r*Hh+lane]) + gcnb[L*Hh+lane];
        d_hP[r*Hh+lane]=v;
        red1[w>>1][lane]=v; red2[w>>1][lane]=v*v;
    }
    __syncthreads();
    if (w==0){
        float s1=0.f, s2=0.f;
        #pragma unroll
        for (int q=0;q<4;q++){ s1+=red1[q][lane]; s2+=red2[q][lane]; }
        d_p1[blockIdx.x*32+lane]=s1; d_p2[blockIdx.x*32+lane]=s2;
    }
}

__global__ void k_hw1(const float* __restrict__ gcnW) {
    int w = threadIdx.x>>5, lane = threadIdx.x&31;
    int r = blockIdx.x*8 + w;
    float s1=0.f, s2=0.f;
    #pragma unroll 4
    for (int b=0;b<NAGG;b++){ s1+=d_p1[b*32+lane]; s2+=d_p2[b*32+lane]; }
    float mean = s1/(float)Nn;
    float inv  = rsqrtf(s2/(float)Nn - mean*mean + 1e-5f);
    float hv = fmaxf((d_hP[r*Hh+lane]-mean)*inv, 0.f);
    float acc = 0.f;
    #pragma unroll
    for (int k=0;k<32;k++) acc += __shfl_sync(0xffffffffu,hv,k) * gcnW[Hh*Hh + k*Hh+lane];
    d_hT[r*Hh+lane] = d_dinv[r]*acc;
}

__global__ void k_norm1() {
    int w = threadIdx.x>>5, lane = threadIdx.x&31;
    int r = blockIdx.x*8 + w;
    float s1=0.f, s2=0.f;
    #pragma unroll 4
    for (int b=0;b<NAGG;b++){ s1+=d_p1[b*32+lane]; s2+=d_p2[b*32+lane]; }
    float mean = s1/(float)Nn;
    float inv  = rsqrtf(s2/(float)Nn - mean*mean + 1e-5f);
    d_h[r*Hh+lane] = fmaxf((d_hP[r*Hh+lane]-mean)*inv, 0.f);
}

// ================= edge MLPs (warp per padded CSR slot) =================
__global__ void k_mlp(const float* __restrict__ W1, const float* __restrict__ b1,
                      const float* __restrict__ W2, const float* __restrict__ b2) {
    int w = threadIdx.x>>5, lane = threadIdx.x&31;
    int s = blockIdx.x*8 + w;                 // 0..Nn*STR-1
    int u = s/STR, idx = s - u*STR;
    if (idx >= d_cnt[u]) return;
    int v = d_col[s];
    float hu = d_h[u*Hh+lane], hv = d_h[v*Hh+lane];
    float x1 = b1[lane], x2 = b2[lane];
    #pragma unroll
    for (int k=0;k<32;k++){
        float a = __shfl_sync(0xffffffffu,hu,k);
        float b = __shfl_sync(0xffffffffu,hv,k);
        x1 += a*W1[k*Hh+lane] + b*W1[(k+32)*Hh+lane];
        x2 += a*W2[k*Hh+lane] + b*W2[(k+32)*Hh+lane];
    }
    d_xe [s*Hh+lane]=fmaxf(x1,0.f);
    d_mul[s*Hh+lane]=fmaxf(x2,0.f);
}

// ================= hot kernel: two-phase flat stream + value prefetch =================
__global__ void __launch_bounds__(256,3) k_z(const float* __restrict__ W3,
                                             const float* __restrict__ b3v) {
    __shared__ unsigned long long sW[512];     // packed W3 pairs
    __shared__ float sC[8][1024];              // per-warp 32x32 C buffer
    __shared__ float sr1[8][32], sr2[8][32];
    __shared__ int src[8];
    int tid = threadIdx.x, w = tid>>5, lane = tid&31;

    #pragma unroll
    for (int f=tid; f<512; f+=256){
        int t = f>>5, ln = f&31;
        sW[f] = pk2(W3[(2*t)*Hh+ln], W3[(2*t+1)*Hh+ln]);
    }
    __syncthreads();

    int wid = blockIdx.x*8 + w;            // 0..18431
    int i = wid/24;
    int wrd = wid - i*24;
    int ij0 = i*Nn + wrd*32;

    int start = d_ijstart[ij0+lane];
    int end   = d_ijend  [ij0+lane];
    unsigned mA = d_abits[i*NW + wrd];
    unsigned mN = d_nbits[i*NW + wrd];
    unsigned hasP = __ballot_sync(0xffffffffu, end>start);
    unsigned mM = mA | hasP;
    d_maskb[ij0+lane] = (unsigned char)((mM>>lane)&1u);
    int c0 = __popc(mM);

    float s1=0.f, s2=0.f;
    if (mM) {
        float* sCw = sC[w];
        {
            float4 z4 = make_float4(0.f,0.f,0.f,0.f);
            float4* p4 = (float4*)sCw;
            #pragma unroll
            for (int t=lane; t<256; t+=32) p4[t]=z4;
        }
        __syncwarp();

        // ---- phase A: flat pair stream; desc 2 groups ahead, values 1 group ahead ----
        int winS = __shfl_sync(0xffffffffu, start, 0);
        int winE = __shfl_sync(0xffffffffu, end, 31);
        const int* prow = d_pair1 + i*BUD;
        const int eb = i*STR*Hh;
        int t = winS;
        if (winE - winS >= 8) {
            int d0[4], d1[4]; float p0[4];
            #pragma unroll
            for (int q=0;q<4;q++) d0[q]=prow[t+q];
            #pragma unroll
            for (int q=0;q<4;q++) d1[q]=prow[t+4+q];
            #pragma unroll
            for (int q=0;q<4;q++){
                int e = eb + ((d0[q]>>17)&127)*Hh;
                int f = (d0[q]&0x1FFFF)*Hh;
                p0[q] = d_xe[e+lane]*d_mul[f+lane];
            }
            t += 8;
            while (t+4 <= winE){
                int d2[4];
                #pragma unroll
                for (int q=0;q<4;q++) d2[q]=prow[t+q];
                float p1[4];
                #pragma unroll
                for (int q=0;q<4;q++){
                    int e = eb + ((d1[q]>>17)&127)*Hh;
                    int f = (d1[q]&0x1FFFF)*Hh;
                    p1[q] = d_xe[e+lane]*d_mul[f+lane];
                }
                #pragma unroll
                for (int q=0;q<4;q++) sCw[(d0[q]>>24)*Hh+lane] += p0[q];
                #pragma unroll
                for (int q=0;q<4;q++){ d0[q]=d1[q]; p0[q]=p1[q]; d1[q]=d2[q]; }
                t += 4;
            }
            // drain d0 then d1
            float p1[4];
            #pragma unroll
            for (int q=0;q<4;q++){
                int e = eb + ((d1[q]>>17)&127)*Hh;
                int f = (d1[q]&0x1FFFF)*Hh;
                p1[q] = d_xe[e+lane]*d_mul[f+lane];
            }
            #pragma unroll
            for (int q=0;q<4;q++) sCw[(d0[q]>>24)*Hh+lane] += p0[q];
            #pragma unroll
            for (int q=0;q<4;q++) sCw[(d1[q]>>24)*Hh+lane] += p1[q];
        }
        for (; t<winE; t++){
            int p = prow[t];
            int e = eb + ((p>>17)&127)*Hh;
            int f = (p&0x1FFFF)*Hh;
            sCw[(p>>24)*Hh+lane] += d_xe[e+lane]*d_mul[f+lane];
        }
        __syncwarp();

        // ---- phase B: z = C@W3 + af*W3[32] + b3 ; moments ; sparse z store ----
        float w3last = W3[32*Hh+lane];
        float bb = b3v[lane];
        unsigned rem = mM;
        while (rem){
            int b = __ffs(rem)-1; rem &= rem-1;
            const ulonglong2* Cj = (const ulonglong2*)(sCw + b*Hh);
            unsigned long long a0=0ull, a1=0ull;
            #pragma unroll
            for (int q=0;q<4;q++){
                ulonglong2 cA = Cj[q];
                ulonglong2 cB = Cj[q+4];
                fma2(a0, cA.x, sW[(2*q)*32+lane]);     fma2(a0, cA.y, sW[(2*q+1)*32+lane]);
                fma2(a1, cB.x, sW[(2*q+8)*32+lane]);   fma2(a1, cB.y, sW[(2*q+9)*32+lane]);
            }
            float acc = bb + upk_sum(a0) + upk_sum(a1) + (((mA>>b)&1u) ? w3last : 0.f);
            s1 += acc; s2 += acc*acc;
            if ((mN>>b)&1u) d_z[(size_t)(ij0+b)*Hh + lane] = acc;
        }
    }
    sr1[w][lane]=s1; sr2[w][lane]=s2; if (lane==0) src[w]=c0;
    __syncthreads();
    if (w==0){
        float a=0.f, b=0.f;
        #pragma unroll
        for (int r=0;r<8;r++){ a+=sr1[r][lane]; b+=sr2[r][lane]; }
        atomicAdd(&d_S1[lane], a);
        atomicAdd(&d_S2[lane], b);
        if (lane==0){ int cc=0; for (int r=0;r<8;r++) cc+=src[r]; atomicAdd(&d_cntM, cc); }
    }
}

// ================= output =================
__global__ void k_pos(const int* __restrict__ pos, const float* __restrict__ linW,
                      const float* __restrict__ linb, float* __restrict__ out) {
    int w = threadIdx.x>>5, lane = threadIdx.x&31;
    int p = blockIdx.x*8 + w;
    float cnt = (float)d_cntM;
    float mean = d_S1[lane]/cnt;
    float inv  = rsqrtf(d_S2[lane]/cnt - mean*mean + 1e-5f);
    int p0 = pos[2*p], p1 = pos[2*p+1];
    float acc = d_h[p0*Hh+lane]*d_h[p1*Hh+lane]*linW[Hh+lane];
    if (d_maskb[p0*Nn+p1]) {
        float z1 = d_z[((size_t)p0*Nn+p1)*Hh+lane];
        float z2 = d_z[((size_t)p1*Nn+p0)*Hh+lane];
        acc += fmaxf((z1-mean)*inv,0.f)*fmaxf((z2-mean)*inv,0.f)*linW[lane];
    }
    for (int o=16;o;o>>=1) acc += __shfl_down_sync(0xffffffffu, acc, o);
    if (lane==0) out[p] = acc + linb[0];
}

// ================= launch =================
extern "C" void kernel_launch(void* const* d_in, const int* in_sizes, int n_in,
                              void* d_out, int out_size) {
    const int*   x    = (const int*)  d_in[0];
    const int*   ei   = (const int*)  d_in[1];
    const int*   pos  = (const int*)  d_in[2];
    const float* emb  = (const float*)d_in[3];
    const float* gcnW = (const float*)d_in[4];
    const float* gcnb = (const float*)d_in[5];
    const float* W1   = (const float*)d_in[6];
    const float* b1   = (const float*)d_in[7];
    const float* W2   = (const float*)d_in[8];
    const float* b2   = (const float*)d_in[9];
    const float* W3   = (const float*)d_in[10];
    const float* b3   = (const float*)d_in[11];
    const float* linW = (const float*)d_in[12];
    const float* linb = (const float*)d_in[13];
    float* out = (float*)d_out;

    k_zero   <<<96, 256>>>(x, emb);
    k_sf     <<<96, 256>>>(ei, pos);
    k_build  <<<Nn, 256>>>();
    k_hw0    <<<96, 256>>>(gcnW);
    k_agg<0> <<<NAGG,256>>>(gcnb);
    k_hw1    <<<96, 256>>>(gcnW);
    k_agg<1> <<<NAGG,256>>>(gcnb);
    k_norm1  <<<96, 256>>>();
    k_mlp    <<<Nn*STR/8,256>>>(W1,b1,W2,b2);
    k_z      <<<Nn*NW/8,256>>>(W3,b3);
    k_pos    <<<Pp/8,256>>>(pos, linW, linb, out);
}

// round 9
// speedup vs baseline: 1.9392x; 1.0111x over previous
#include <cuda_runtime.h>

#define Nn 768
#define Hh 32
#define Ee 24576
#define Pp 4096
#define NW 24              // 768/32 bitmask words per row
#define STR 96             // fixed CSR stride per row
#define BUD 6144           // per-row pair budget
#define NAGG 192

// ---------------- scratch ----------------
__device__ unsigned d_abits[Nn*NW];     // zeroed by k_z after last read
__device__ unsigned d_nbits[Nn*NW];     // zeroed by k_z after last read
__device__ unsigned char d_maskb[Nn*Nn];
__device__ float d_dinv[Nn];
__device__ float d_h [Nn*Hh];
__device__ float d_hT[Nn*Hh];
__device__ float d_hP[Nn*Hh];
__device__ int   d_cnt [Nn];            // zeroed by k_z
__device__ int   d_col[Nn*STR];
__device__ int   d_ijstart[Nn*Nn];
__device__ int   d_ijend  [Nn*Nn];
__device__ int   d_pair1[Nn*BUD];       // f | e_local<<17 | j_local<<24
__device__ float d_xe [Nn*STR*Hh];
__device__ float d_mul[Nn*STR*Hh];
__device__ float d_z  [(size_t)Nn*Nn*Hh];
__device__ float d_p1[NAGG*Hh], d_p2[NAGG*Hh];
__device__ float d_S1[Hh], d_S2[Hh];    // zeroed by k_sf
__device__ int   d_cntM;                // zeroed by k_sf

// ---------------- f32x2 helpers ----------------
__device__ __forceinline__ void fma2(unsigned long long& d, unsigned long long a, unsigned long long b){
    asm("fma.rn.f32x2 %0, %1, %2, %0;" : "+l"(d) : "l"(a), "l"(b));
}
__device__ __forceinline__ unsigned long long pk2(float lo, float hi){
    unsigned long long r; asm("mov.b64 %0,{%1,%2};" : "=l"(r) : "f"(lo), "f"(hi)); return r;
}
__device__ __forceinline__ float upk_sum(unsigned long long v){
    float lo, hi; asm("mov.b64 {%0,%1},%2;" : "=f"(lo), "=f"(hi) : "l"(v)); return lo+hi;
}

// ================= setup: scatter bits + fixed-stride CSR + zero stats =================
__global__ void k_sf(const int* __restrict__ ei, const int* __restrict__ pos) {
    int t = blockIdx.x*256 + threadIdx.x;
    if (t < Hh){ d_S1[t]=0.f; d_S2[t]=0.f; }
    if (t == Hh) d_cntM = 0;
    int u = ei[t], v = ei[Ee+t];
    atomicOr(&d_abits[u*NW+(v>>5)], 1u<<(v&31));
    int slot = atomicAdd(&d_cnt[u], 1);
    d_col[u*STR+slot] = v;
    if (t < Pp){
        int a=pos[2*t], b=pos[2*t+1];
        atomicOr(&d_nbits[a*NW+(b>>5)], 1u<<(b&31));
        atomicOr(&d_nbits[b*NW+(a>>5)], 1u<<(a&31));
    }
}

// ================= per-row pair build (768 blocks) =================
__global__ void __launch_bounds__(256) k_build() {
    __shared__ int scnt[Nn];
    __shared__ int scur[Nn];
    __shared__ int wsum[8];
    int tid = threadIdx.x, w = tid>>5, lane = tid&31;
    int i = blockIdx.x;
    for (int t=tid; t<Nn; t+=256) scnt[t]=0;
    __syncthreads();
    int es = i*STR, deg = d_cnt[i];
    for (int e=w; e<deg; e+=8){
        int k = d_col[es+e];
        int fk = k*STR, dk = d_cnt[k];
        for (int f=lane; f<dk; f+=32) atomicAdd(&scnt[d_col[fk+f]], 1);
    }
    __syncthreads();
    int lo = tid*3;
    int c0=scnt[lo], c1=scnt[lo+1], c2=scnt[lo+2];
    int s = c0+c1+c2, sc = s;
    #pragma unroll
    for (int o=1;o<32;o<<=1){ int t2=__shfl_up_sync(0xffffffffu,sc,o); if (lane>=o) sc+=t2; }
    if (lane==31) wsum[w]=sc;
    __syncthreads();
    if (w==0){
        int v = (lane<8) ? wsum[lane] : 0;
        int p = v;
        #pragma unroll
        for (int o=1;o<8;o<<=1){ int t2=__shfl_up_sync(0xffffffffu,p,o); if (lane>=o) p+=t2; }
        if (lane<8) wsum[lane]=p-v;
    }
    __syncthreads();
    int b0 = wsum[w] + sc - s;
    scur[lo]=b0; scur[lo+1]=b0+c0; scur[lo+2]=b0+c0+c1;
    d_ijstart[i*Nn+lo]  =b0;        d_ijend[i*Nn+lo]  =b0+c0;
    d_ijstart[i*Nn+lo+1]=b0+c0;     d_ijend[i*Nn+lo+1]=b0+c0+c1;
    d_ijstart[i*Nn+lo+2]=b0+c0+c1;  d_ijend[i*Nn+lo+2]=b0+c0+c1+c2;
    __syncthreads();
    int* prow = d_pair1 + i*BUD;
    for (int e=w; e<deg; e+=8){
        int k = d_col[es+e];
        int fk = k*STR, dk = d_cnt[k];
        for (int f=lane; f<dk; f+=32){
            int j = d_col[fk+f];
            int slot = atomicAdd(&scur[j], 1);
            prow[slot] = (fk+f) | (e<<17) | ((j&31)<<24);
        }
    }
}

// ================= GCN =================
// embed + dinv + hT = dinv * (emb[x] @ W0)
__global__ void k_hw0(const int* __restrict__ x, const float* __restrict__ emb,
                      const float* __restrict__ gcnW) {
    int w = threadIdx.x>>5, lane = threadIdx.x&31;
    int r = blockIdx.x*8 + w;
    int s = (lane<NW) ? __popc(d_abits[r*NW+lane]) : 0;
    #pragma unroll
    for (int o=16;o;o>>=1) s += __shfl_xor_sync(0xffffffffu, s, o);
    float dv = rsqrtf((float)s + 1.0f);
    if (lane==0) d_dinv[r] = dv;
    float hv = emb[x[r]*Hh+lane];
    float acc = 0.f;
    #pragma unroll
    for (int k=0;k<32;k++) acc += __shfl_sync(0xffffffffu,hv,k) * gcnW[k*Hh+lane];
    d_hT[r*Hh+lane] = dv*acc;
}

template<int L>
__global__ void k_agg(const float* __restrict__ gcnb) {
    __shared__ float sAg[8][32];
    __shared__ float red1[4][32], red2[4][32];
    int w = threadIdx.x>>5, lane = threadIdx.x&31;
    int r = blockIdx.x*4 + (w>>1);
    int half = w&1;
    float aggv = 0.f;
    #pragma unroll 1
    for (int wd=half*12; wd<half*12+12; wd++){
        unsigned m = d_abits[r*NW+wd];
        int jb = wd*32;
        while (m){ int b=__ffs(m)-1; m&=m-1; aggv += d_hT[(jb+b)*Hh+lane]; }
    }
    sAg[w][lane]=aggv;
    __syncthreads();
    if (half==0){
        float tot = sAg[w][lane] + sAg[w+1][lane];
        float v = d_dinv[r]*(tot + d_hT[r*Hh+lane]) + gcnb[L*Hh+lane];
        d_hP[r*Hh+lane]=v;
        red1[w>>1][lane]=v; red2[w>>1][lane]=v*v;
    }
    __syncthreads();
    if (w==0){
        float s1=0.f, s2=0.f;
        #pragma unroll
        for (int q=0;q<4;q++){ s1+=red1[q][lane]; s2+=red2[q][lane]; }
        d_p1[blockIdx.x*32+lane]=s1; d_p2[blockIdx.x*32+lane]=s2;
    }
}

__global__ void k_hw1(const float* __restrict__ gcnW) {
    int w = threadIdx.x>>5, lane = threadIdx.x&31;
    int r = blockIdx.x*8 + w;
    float s1=0.f, s2=0.f;
    #pragma unroll 4
    for (int b=0;b<NAGG;b++){ s1+=d_p1[b*32+lane]; s2+=d_p2[b*32+lane]; }
    float mean = s1/(float)Nn;
    float inv  = rsqrtf(s2/(float)Nn - mean*mean + 1e-5f);
    float hv = fmaxf((d_hP[r*Hh+lane]-mean)*inv, 0.f);
    float acc = 0.f;
    #pragma unroll
    for (int k=0;k<32;k++) acc += __shfl_sync(0xffffffffu,hv,k) * gcnW[Hh*Hh + k*Hh+lane];
    d_hT[r*Hh+lane] = d_dinv[r]*acc;
}

__global__ void k_norm1() {
    int w = threadIdx.x>>5, lane = threadIdx.x&31;
    int r = blockIdx.x*8 + w;
    float s1=0.f, s2=0.f;
    #pragma unroll 4
    for (int b=0;b<NAGG;b++){ s1+=d_p1[b*32+lane]; s2+=d_p2[b*32+lane]; }
    float mean = s1/(float)Nn;
    float inv  = rsqrtf(s2/(float)Nn - mean*mean + 1e-5f);
    d_h[r*Hh+lane] = fmaxf((d_hP[r*Hh+lane]-mean)*inv, 0.f);
}

// ================= edge MLPs: 4 edges per warp =================
__global__ void k_mlp(const float* __restrict__ W1, const float* __restrict__ b1,
                      const float* __restrict__ W2, const float* __restrict__ b2) {
    int w = threadIdx.x>>5, lane = threadIdx.x&31;
    int wid = blockIdx.x*8 + w;            // 0..Nn*STR/4-1
    int s0 = wid*4;                        // 4 slots, all in row u (96%4==0)
    int u = s0/STR, idx0 = s0 - u*STR;
    int deg = d_cnt[u];
    if (idx0 >= deg) return;               // warp-uniform early exit
    int nv = min(deg - idx0, 4);
    float hu = d_h[u*Hh+lane];
    float hv[4], x1[4], x2[4];
    #pragma unroll
    for (int q=0;q<4;q++){
        int v = (q<nv) ? d_col[s0+q] : d_col[s0];
        hv[q] = d_h[v*Hh+lane];
        x1[q] = b1[lane]; x2[q] = b2[lane];
    }
    #pragma unroll 4
    for (int k=0;k<32;k++){
        float w1a=W1[k*Hh+lane], w1b=W1[(k+32)*Hh+lane];
        float w2a=W2[k*Hh+lane], w2b=W2[(k+32)*Hh+lane];
        float a = __shfl_sync(0xffffffffu,hu,k);
        #pragma unroll
        for (int q=0;q<4;q++){
            float b = __shfl_sync(0xffffffffu,hv[q],k);
            x1[q] += a*w1a + b*w1b;
            x2[q] += a*w2a + b*w2b;
        }
    }
    #pragma unroll
    for (int q=0;q<4;q++){
        if (q<nv){
            d_xe [(s0+q)*Hh+lane]=fmaxf(x1[q],0.f);
            d_mul[(s0+q)*Hh+lane]=fmaxf(x2[q],0.f);
        }
    }
}

// ================= hot kernel: block = row; xe staged in smem =================
__global__ void __launch_bounds__(256,4) k_z(const float* __restrict__ W3,
                                             const float* __restrict__ b3v) {
    __shared__ unsigned long long sW[512];     // packed W3 pairs (4 KB)
    __shared__ float sxe[STR*Hh];              // row i's xe (12 KB)
    __shared__ float sC[8][1024];              // per-warp C buffer (32 KB)
    __shared__ float sr1[8][32], sr2[8][32];
    __shared__ int src[8];
    int tid = threadIdx.x, w = tid>>5, lane = tid&31;
    int i = blockIdx.x;

    #pragma unroll
    for (int f=tid; f<512; f+=256){
        int t = f>>5, ln = f&31;
        sW[f] = pk2(W3[(2*t)*Hh+ln], W3[(2*t+1)*Hh+ln]);
    }
    int deg = d_cnt[i];
    {   // stage xe rows for this row's edges
        const float4* src4 = (const float4*)(d_xe + i*STR*Hh);
        float4* dst4 = (float4*)sxe;
        for (int t=tid; t<deg*8; t+=256) dst4[t]=src4[t];
    }
    __syncthreads();

    float w3last = W3[32*Hh+lane];
    float bb = b3v[lane];
    float s1=0.f, s2=0.f; int c0=0;
    float* sCw = sC[w];
    const int* prow = d_pair1 + i*BUD;

    #pragma unroll 1
    for (int win=w; win<24; win+=8){
        int ij0 = i*Nn + win*32;
        int start = d_ijstart[ij0+lane];
        int end   = d_ijend  [ij0+lane];
        unsigned mA = d_abits[i*NW + win];
        unsigned mN = d_nbits[i*NW + win];
        unsigned hasP = __ballot_sync(0xffffffffu, end>start);
        unsigned mM = mA | hasP;
        d_maskb[ij0+lane] = (unsigned char)((mM>>lane)&1u);
        c0 += __popc(mM);
        if (lane==0){ d_abits[i*NW+win]=0u; d_nbits[i*NW+win]=0u; }  // reset for next replay

        if (mM){
            {
                float4 z4 = make_float4(0.f,0.f,0.f,0.f);
                float4* p4 = (float4*)sCw;
                #pragma unroll
                for (int t=lane; t<256; t+=32) p4[t]=z4;
            }
            __syncwarp();

            // ---- phase A: flat stream; mul-LDG one group ahead; xe from smem ----
            int winS = __shfl_sync(0xffffffffu, start, 0);
            int winE = __shfl_sync(0xffffffffu, end, 31);
            int t = winS;
            if (winE - winS >= 8){
                int d0[4], d1[4]; float m0[4];
                #pragma unroll
                for (int q=0;q<4;q++) d0[q]=prow[t+q];
                #pragma unroll
                for (int q=0;q<4;q++) d1[q]=prow[t+4+q];
                #pragma unroll
                for (int q=0;q<4;q++) m0[q]=d_mul[(d0[q]&0x1FFFF)*Hh+lane];
                t += 8;
                while (t+4 <= winE){
                    int d2[4];
                    #pragma unroll
                    for (int q=0;q<4;q++) d2[q]=prow[t+q];
                    float m1[4];
                    #pragma unroll
                    for (int q=0;q<4;q++) m1[q]=d_mul[(d1[q]&0x1FFFF)*Hh+lane];
                    #pragma unroll
                    for (int q=0;q<4;q++)
                        sCw[(d0[q]>>24)*Hh+lane] += sxe[((d0[q]>>17)&127)*Hh+lane]*m0[q];
                    #pragma unroll
                    for (int q=0;q<4;q++){ d0[q]=d1[q]; m0[q]=m1[q]; d1[q]=d2[q]; }
                    t += 4;
                }
                float m1[4];
                #pragma unroll
                for (int q=0;q<4;q++) m1[q]=d_mul[(d1[q]&0x1FFFF)*Hh+lane];
                #pragma unroll
                for (int q=0;q<4;q++)
                    sCw[(d0[q]>>24)*Hh+lane] += sxe[((d0[q]>>17)&127)*Hh+lane]*m0[q];
                #pragma unroll
                for (int q=0;q<4;q++)
                    sCw[(d1[q]>>24)*Hh+lane] += sxe[((d1[q]>>17)&127)*Hh+lane]*m1[q];
            }
            for (; t<winE; t++){
                int p = prow[t];
                sCw[(p>>24)*Hh+lane] += sxe[((p>>17)&127)*Hh+lane]*d_mul[(p&0x1FFFF)*Hh+lane];
            }
            __syncwarp();

            // ---- phase B ----
            unsigned rem = mM;
            while (rem){
                int b = __ffs(rem)-1; rem &= rem-1;
                const ulonglong2* Cj = (const ulonglong2*)(sCw + b*Hh);
                unsigned long long a0=0ull, a1=0ull;
                #pragma unroll
                for (int q=0;q<4;q++){
                    ulonglong2 cA = Cj[q];
                    ulonglong2 cB = Cj[q+4];
                    fma2(a0, cA.x, sW[(2*q)*32+lane]);     fma2(a0, cA.y, sW[(2*q+1)*32+lane]);
                    fma2(a1, cB.x, sW[(2*q+8)*32+lane]);   fma2(a1, cB.y, sW[(2*q+9)*32+lane]);
                }
                float acc = bb + upk_sum(a0) + upk_sum(a1) + (((mA>>b)&1u) ? w3last : 0.f);
                s1 += acc; s2 += acc*acc;
                if ((mN>>b)&1u) d_z[(size_t)(ij0+b)*Hh + lane] = acc;
            }
        }
    }
    sr1[w][lane]=s1; sr2[w][lane]=s2; if (lane==0) src[w]=c0;
    __syncthreads();
    if (w==0){
        float a=0.f, b=0.f;
        #pragma unroll
        for (int r=0;r<8;r++){ a+=sr1[r][lane]; b+=sr2[r][lane]; }
        atomicAdd(&d_S1[lane], a);
        atomicAdd(&d_S2[lane], b);
        if (lane==0){ int cc=0; for (int r=0;r<8;r++) cc+=src[r]; atomicAdd(&d_cntM, cc); }
    }
    if (tid==0) d_cnt[i]=0;                    // reset for next replay
}

// ================= output =================
__global__ void k_pos(const int* __restrict__ pos, const float* __restrict__ linW,
                      const float* __restrict__ linb, float* __restrict__ out) {
    int w = threadIdx.x>>5, lane = threadIdx.x&31;
    int p = blockIdx.x*8 + w;
    float cnt = (float)d_cntM;
    float mean = d_S1[lane]/cnt;
    float inv  = rsqrtf(d_S2[lane]/cnt - mean*mean + 1e-5f);
    int p0 = pos[2*p], p1 = pos[2*p+1];
    float acc = d_h[p0*Hh+lane]*d_h[p1*Hh+lane]*linW[Hh+lane];
    if (d_maskb[p0*Nn+p1]) {
        float z1 = d_z[((size_t)p0*Nn+p1)*Hh+lane];
        float z2 = d_z[((size_t)p1*Nn+p0)*Hh+lane];
        acc += fmaxf((z1-mean)*inv,0.f)*fmaxf((z2-mean)*inv,0.f)*linW[lane];
    }
    for (int o=16;o;o>>=1) acc += __shfl_down_sync(0xffffffffu, acc, o);
    if (lane==0) out[p] = acc + linb[0];
}

// ================= launch =================
extern "C" void kernel_launch(void* const* d_in, const int* in_sizes, int n_in,
                              void* d_out, int out_size) {
    const int*   x    = (const int*)  d_in[0];
    const int*   ei   = (const int*)  d_in[1];
    const int*   pos  = (const int*)  d_in[2];
    const float* emb  = (const float*)d_in[3];
    const float* gcnW = (const float*)d_in[4];
    const float* gcnb = (const float*)d_in[5];
    const float* W1   = (const float*)d_in[6];
    const float* b1   = (const float*)d_in[7];
    const float* W2   = (const float*)d_in[8];
    const float* b2   = (const float*)d_in[9];
    const float* W3   = (const float*)d_in[10];
    const float* b3   = (const float*)d_in[11];
    const float* linW = (const float*)d_in[12];
    const float* linb = (const float*)d_in[13];
    float* out = (float*)d_out;

    k_sf     <<<96, 256>>>(ei, pos);
    k_build  <<<Nn, 256>>>();
    k_hw0    <<<96, 256>>>(x, emb, gcnW);
    k_agg<0> <<<NAGG,256>>>(gcnb);
    k_hw1    <<<96, 256>>>(gcnW);
    k_agg<1> <<<NAGG,256>>>(gcnb);
    k_norm1  <<<96, 256>>>();
    k_mlp    <<<Nn*STR/32,256>>>(W1,b1,W2,b2);
    k_z      <<<Nn, 256>>>(W3,b3);
    k_pos    <<<Pp/8,256>>>(pos, linW, linb, out);
}